// round 9
// baseline (speedup 1.0000x reference)
#include <cuda_runtime.h>
#include <math.h>

// Problem dims
#define BB_ 16
#define T_ 64
#define S_ 32
#define F_ 128
#define H_ 128
#define NH_ 4

// ---------------- scratch (no allocations allowed) ----------------
__device__ float g_q[BB_*NH_*H_*S_];     // 262144
__device__ float g_k[BB_*NH_*H_*S_];
__device__ float g_v[BB_*NH_*H_*S_];
__device__ float g_att4[BB_*NH_*H_*S_];
__device__ float g_part[3*32*BB_*H_];    // 196608  gate split-K partials
__device__ float g_fc[BB_*2*H_];         // 4096    fc out (mu|logvar)
__device__ float g_h2[BB_*H_];           // 2048    decoder h2

__device__ __forceinline__ unsigned int rotl32_(unsigned int v, int d){ return (v << d) | (v >> (32 - d)); }

// Neumaier compensated accumulate: s += p with running compensation c.
__device__ __forceinline__ void kadd_(float& s, float& c, float p){
  float t = s + p;
  c += (fabsf(s) >= fabsf(p)) ? ((s - t) + p) : ((p - t) + s);
  s = t;
}

// Exact JAX threefry2x32 (20 rounds), key = (k0, k1)
__device__ __forceinline__ void threefry2x32_(unsigned int k0, unsigned int k1,
    unsigned int c0, unsigned int c1, unsigned int& o0, unsigned int& o1)
{
  unsigned int ks2 = k0 ^ k1 ^ 0x1BD11BDAu;
  unsigned int x0 = c0 + k0, x1 = c1 + k1;
  const int ra[4] = {13,15,26,6};
  const int rb[4] = {17,29,16,24};
  #pragma unroll
  for (int i=0;i<4;i++){ x0 += x1; x1 = rotl32_(x1, ra[i]); x1 ^= x0; }
  x0 += k1; x1 += ks2 + 1u;
  #pragma unroll
  for (int i=0;i<4;i++){ x0 += x1; x1 = rotl32_(x1, rb[i]); x1 ^= x0; }
  x0 += ks2; x1 += k0 + 2u;
  #pragma unroll
  for (int i=0;i<4;i++){ x0 += x1; x1 = rotl32_(x1, ra[i]); x1 ^= x0; }
  x0 += k0; x1 += k1 + 3u;
  #pragma unroll
  for (int i=0;i<4;i++){ x0 += x1; x1 = rotl32_(x1, rb[i]); x1 ^= x0; }
  x0 += k1; x1 += ks2 + 4u;
  #pragma unroll
  for (int i=0;i<4;i++){ x0 += x1; x1 = rotl32_(x1, ra[i]); x1 ^= x0; }
  x0 += ks2; x1 += k0 + 5u;
  o0 = x0; o1 = x1;
}

// ---------------- K1: fused hid + q/k/v head projections ----------------
// grid 256: (b, n, h-tile of 32). hid recomputed per head (cheap) to save a launch.
__global__ void __launch_bounds__(256) headsF_kernel(
    const float* __restrict__ xsrc,
    const float* __restrict__ w_enc, const float* __restrict__ b_enc,
    const float* __restrict__ wq, const float* __restrict__ bq,
    const float* __restrict__ wk, const float* __restrict__ bk,
    const float* __restrict__ wv, const float* __restrict__ bv)
{
  __shared__ float xs[S_*129];
  __shared__ float hsm[32*33];
  __shared__ float wqn[S_*33], wkn[S_*33], wvn[S_*33];
  int b = blockIdx.x >> 4, n = (blockIdx.x >> 2) & 3, ht = blockIdx.x & 3;
  int tid = threadIdx.x;
  const float* xb = xsrc + (size_t)b*(T_*S_*F_) + (size_t)(T_-1)*(S_*F_);
  for (int i = tid; i < S_*F_; i += 256) {
    int s = i >> 7, f = i & 127;
    xs[s*129+f] = xb[i];
  }
  for (int i = tid; i < S_*S_; i += 256) {
    int sp = i >> 5, s = i & 31;
    wqn[sp*33+s] = wq[sp*(S_*NH_) + n*S_ + s];
    wkn[sp*33+s] = wk[sp*(S_*NH_) + n*S_ + s];
    wvn[sp*33+s] = wv[sp*(S_*NH_) + n*S_ + s];
  }
  __syncthreads();
  // hid[h][s] for this 32-h tile (compensated, same order as before)
  for (int i = tid; i < 32*S_; i += 256) {
    int hl = i >> 5, s = i & 31;
    int h = ht*32 + hl;
    float acc = 0.f, cc = 0.f;
    #pragma unroll 8
    for (int f = 0; f < F_; f++)
      kadd_(acc, cc, xs[s*129+f] * w_enc[f*H_ + h]);
    hsm[hl*33+s] = (acc + cc) + b_enc[h];
  }
  __syncthreads();
  const float scale = 0.08838834764831845f; // 1/sqrt(H)
  size_t base = ((size_t)(b*NH_ + n))*(H_*S_);
  for (int i = tid; i < 32*S_; i += 256) {
    int hl = i >> 5, s = i & 31;
    float aq = 0.f, cq = 0.f, ak = 0.f, ck = 0.f, av = 0.f, cv = 0.f;
    #pragma unroll
    for (int sp = 0; sp < S_; sp++) {
      float hv = hsm[hl*33+sp];
      kadd_(aq, cq, hv * wqn[sp*33+s]);
      kadd_(ak, ck, hv * wkn[sp*33+s]);
      kadd_(av, cv, hv * wvn[sp*33+s]);
    }
    size_t o = base + (size_t)(ht*32+hl)*S_ + s;
    g_q[o] = ((aq + cq) + bq[n*S_+s]) * scale;
    g_k[o] = (ak + ck) + bk[n*S_+s];
    g_v[o] = (av + cv) + bv[n*S_+s];
  }
}

// ---------------- K2: attention (softmax over g=H, per (b,n, 32 q-rows)) ----------------
__global__ void __launch_bounds__(256) attn_kernel()
{
  __shared__ float ksm[H_*33];
  __shared__ float vsm[H_*33];
  __shared__ float qsm[32*33];
  __shared__ float prob[8*128];
  int blk = blockIdx.x;          // (b*4+n)*4 + hq
  int bn = blk >> 2, hq = blk & 3;
  int tid = threadIdx.x;
  size_t base = (size_t)bn * (H_*S_);
  for (int i = tid; i < H_*S_; i += 256) {
    ksm[(i>>5)*33 + (i&31)] = g_k[base + i];
    vsm[(i>>5)*33 + (i&31)] = g_v[base + i];
  }
  for (int i = tid; i < 32*S_; i += 256) {
    qsm[(i>>5)*33 + (i&31)] = g_q[base + (size_t)hq*32*S_ + i];
  }
  __syncthreads();
  int warp = tid >> 5, lane = tid & 31;
  float* pw = prob + warp*128;
  #pragma unroll
  for (int r = 0; r < 4; r++) {
    int hh = warp*4 + r;
    float lg[4];
    #pragma unroll
    for (int j = 0; j < 4; j++) {
      int g = lane + 32*j;
      float acc = 0.f, cc = 0.f;
      #pragma unroll
      for (int s = 0; s < S_; s++)
        kadd_(acc, cc, qsm[hh*33+s] * ksm[g*33+s]);
      lg[j] = acc + cc;
    }
    float m = fmaxf(fmaxf(lg[0],lg[1]), fmaxf(lg[2],lg[3]));
    #pragma unroll
    for (int o = 16; o; o >>= 1) m = fmaxf(m, __shfl_xor_sync(0xffffffffu, m, o));
    float ssum = 0.f;
    #pragma unroll
    for (int j = 0; j < 4; j++){ lg[j] = expf(lg[j]-m); ssum += lg[j]; }
    #pragma unroll
    for (int o = 16; o; o >>= 1) ssum += __shfl_xor_sync(0xffffffffu, ssum, o);
    float inv = 1.f/ssum;
    #pragma unroll
    for (int j = 0; j < 4; j++) pw[lane + 32*j] = lg[j]*inv;
    __syncwarp();
    float acc = 0.f, cc = 0.f;
    #pragma unroll 8
    for (int g = 0; g < H_; g++)
      kadd_(acc, cc, pw[g] * vsm[g*33+lane]);
    g_att4[base + (size_t)(hq*32+hh)*S_ + lane] = acc + cc;
    __syncwarp();
  }
}

// ---------------- K3: gate GEMM with fused head-mean+ReLU ----------------
// grid 192: gate(3) x chunk(32 of 128) x batch-half(2). a = relu(mean4(att))
// computed on the fly from g_att4 (same float expr as old combine => identical).
__global__ void __launch_bounds__(256) gatesC_kernel(
    const float* __restrict__ Wii, const float* __restrict__ Wig, const float* __restrict__ Wio)
{
  __shared__ float as[8*128];
  int gate = blockIdx.x / 64;
  int rem  = blockIdx.x - gate*64;
  int chunk = rem >> 1, bh = rem & 1;
  const float* Wm = (gate == 0) ? Wii : (gate == 1) ? Wig : Wio;
  int tid = threadIdx.x;
  int j0 = chunk*128;
  for (int i = tid; i < 8*128; i += 256) {
    int bb = i >> 7, j = i & 127;
    int bg = bh*8 + bb;
    size_t bbase = (size_t)bg*4*(H_*S_);
    int hs = j0 + j;
    float v = (g_att4[bbase + hs] + g_att4[bbase + 4096 + hs])
            + (g_att4[bbase + 8192 + hs] + g_att4[bbase + 12288 + hs]);
    v *= 0.25f;
    as[i] = v > 0.f ? v : 0.f;
  }
  __syncthreads();
  int m = tid & 127, half = tid >> 7;
  float acc[4] = {0.f,0.f,0.f,0.f};
  float cmp[4] = {0.f,0.f,0.f,0.f};
  #pragma unroll 2
  for (int j = 0; j < 128; j++) {
    float w = Wm[(size_t)(j0+j)*H_ + m];
    #pragma unroll
    for (int bb = 0; bb < 4; bb++)
      kadd_(acc[bb], cmp[bb], as[(half*4+bb)*128 + j] * w);
  }
  size_t cbase = ((size_t)(gate*32 + chunk))*(BB_*H_);
  #pragma unroll
  for (int bb = 0; bb < 4; bb++)
    g_part[cbase + (bh*8 + half*4 + bb)*H_ + m] = acc[bb] + cmp[bb];
}

// ---------------- K4: reduce + LSTM + fc, one block per batch row ----------------
// grid 16, 256 threads. Per-output summation orders identical to the round-7
// split kernels (reduce: ch 0..31 Kahan; lstm double; fc: mm 0..127 Kahan).
__global__ void __launch_bounds__(256) rlf_kernel(
    const float* __restrict__ w_fc, const float* __restrict__ b_fc)
{
  __shared__ float s_g[384];   // [gate][m] gate pre-activations for this b-row
  __shared__ float s_h[128];   // LSTM h for this b-row
  int b = blockIdx.x, tid = threadIdx.x;
  // 1. reduce split-K chunks for rows r = b*128 + m
  for (int idx = tid; idx < 384; idx += 256) {
    int gate = idx >> 7, m = idx & 127;
    int r = b*128 + m;
    float s = 0.f, c = 0.f;
    #pragma unroll
    for (int ch = 0; ch < 32; ch++)
      kadd_(s, c, g_part[(size_t)(gate*32 + ch)*(BB_*H_) + r]);
    s_g[gate*128 + m] = s + c;
  }
  __syncthreads();
  // 2. LSTM cell in double (c0 = 0 => c = i*g)
  if (tid < 128) {
    double iv = 1.0/(1.0 + exp(-(double)s_g[tid]));
    double gv = tanh((double)s_g[128 + tid]);
    double ov = 1.0/(1.0 + exp(-(double)s_g[256 + tid]));
    s_h[tid] = (float)(ov * tanh(iv * gv));
  }
  __syncthreads();
  // 3. fc: out[b][c] = h[b,:] @ w_fc[:,c] + b_fc[c]
  int c = tid;   // < 256
  float s = 0.f, cc = 0.f;
  #pragma unroll 8
  for (int mm = 0; mm < 128; mm++)
    kadd_(s, cc, s_h[mm] * w_fc[mm*256 + c]);
  g_fc[b*256 + c] = (s + cc) + b_fc[c];
}

// ---------------- K5: reparam + KL ----------------
__global__ void __launch_bounds__(256) kl_kernel(
    unsigned int keylo, float* __restrict__ z_out, float* __restrict__ kl_out)
{
  __shared__ double redd[256];
  int tid = threadIdx.x;
  double kacc = 0.0;
  for (int idx = tid; idx < 2048; idx += 256) {
    int bb = idx >> 7, k = idx & 127;
    float mu = g_fc[bb*256 + k];
    float lv = g_fc[bb*256 + 128 + k];
    // eps via JAX partitionable threefry: counter=(0, idx), key=(0, seed), bits = o0^o1
    unsigned int o0, o1;
    threefry2x32_(0u, keylo, 0u, (unsigned int)idx, o0, o1);
    unsigned int bits = o0 ^ o1;
    float f = __uint_as_float((bits >> 9) | 0x3f800000u) - 1.0f;   // [0,1)
    const float lo = -0.99999994f;                                 // nextafter(-1,0)
    float u = fmaxf(lo, fmaf(f, 2.0f, lo));                        // (1 - lo) rounds to 2.0f
    float eps = 1.4142135623730951f * erfinvf(u);
    z_out[idx] = fmaf(eps, expf(0.5f*lv), mu);
    double dmu = (double)mu, dlv = (double)lv;
    kacc += 1.0 + dlv - dmu*dmu - exp(dlv);
  }
  redd[tid] = kacc;
  __syncthreads();
  for (int o = 128; o; o >>= 1) {
    if (tid < o) redd[tid] += redd[tid + o];
    __syncthreads();
  }
  if (tid == 0) kl_out[0] = (float)(-0.5 * redd[0] * (1.0/2048.0));
}

// ---------------- K6: decode MLP (z -> h1 -> h2), compensated ----------------
__global__ void __launch_bounds__(256) dec_small_kernel(
    const float* __restrict__ z,
    const float* __restrict__ w_d1, const float* __restrict__ b_d1,
    const float* __restrict__ w_d2, const float* __restrict__ b_d2)
{
  __shared__ float zb[2048], h1[2048];
  int tid = threadIdx.x;
  for (int i = tid; i < 2048; i += 256) zb[i] = z[i];
  __syncthreads();
  for (int i = tid; i < 2048; i += 256) {
    int bb = i >> 7, c = i & 127;
    float s = 0.f, cc = 0.f;
    #pragma unroll 8
    for (int j = 0; j < 128; j++)
      kadd_(s, cc, zb[bb*128+j] * w_d1[j*128+c]);
    float acc = (s + cc) + b_d1[c];
    h1[i] = fmaxf(acc, 0.f);
  }
  __syncthreads();
  for (int i = tid; i < 2048; i += 256) {
    int bb = i >> 7, c = i & 127;
    float s = 0.f, cc = 0.f;
    #pragma unroll 8
    for (int j = 0; j < 128; j++)
      kadd_(s, cc, h1[bb*128+j] * w_d2[j*128+c]);
    float acc = (s + cc) + b_d2[c];
    g_h2[i] = fmaxf(acc, 0.f);
  }
}

// ---------------- K7: big decode GEMM h2[16,128] @ w_d3[128,262144] + b_d3 ----------------
// Memory-bound (134 MB of w_d3). Batch pairs packed into f32x2 so the FMA pipe
// keeps up with HBM (dual-FP32 fma.rn.f32x2).
__device__ __forceinline__ unsigned long long pk2_(float a, float b){
  return (unsigned long long)__float_as_uint(a) | ((unsigned long long)__float_as_uint(b) << 32);
}

__global__ void __launch_bounds__(256) big_kernel(
    const float* __restrict__ w_d3, const float* __restrict__ b_d3, float* __restrict__ out)
{
  __shared__ unsigned long long hp[8*128];   // (b-pair, j) packed h2 values
  int tid = threadIdx.x;
  for (int i = tid; i < 1024; i += 256) {
    int p = i >> 7, j = i & 127;
    hp[i] = pk2_(g_h2[(2*p)*128 + j], g_h2[(2*p+1)*128 + j]);
  }
  __syncthreads();
  size_t m2 = (size_t)blockIdx.x*256 + tid;    // float2 column index, < 131072
  const float2* w2 = (const float2*)w_d3;
  float2 bv2 = ((const float2*)b_d3)[m2];
  unsigned long long accx[8], accy[8];
  unsigned long long bx = pk2_(bv2.x, bv2.x), by = pk2_(bv2.y, bv2.y);
  #pragma unroll
  for (int p = 0; p < 8; p++){ accx[p] = bx; accy[p] = by; }
  #pragma unroll 4
  for (int j = 0; j < 128; j++) {
    float2 w = __ldg(&w2[(size_t)j*131072 + m2]);
    unsigned long long wx = pk2_(w.x, w.x), wy = pk2_(w.y, w.y);
    #pragma unroll
    for (int p = 0; p < 8; p++) {
      unsigned long long hpair = hp[p*128 + j];
      asm("fma.rn.f32x2 %0, %1, %2, %3;" : "=l"(accx[p]) : "l"(hpair), "l"(wx), "l"(accx[p]));
      asm("fma.rn.f32x2 %0, %1, %2, %3;" : "=l"(accy[p]) : "l"(hpair), "l"(wy), "l"(accy[p]));
    }
  }
  float2* o2 = (float2*)out;
  #pragma unroll
  for (int p = 0; p < 8; p++) {
    float2 v0, v1;
    v0.x = __uint_as_float((unsigned int)accx[p]);
    v0.y = __uint_as_float((unsigned int)accy[p]);
    v1.x = __uint_as_float((unsigned int)(accx[p] >> 32));
    v1.y = __uint_as_float((unsigned int)(accy[p] >> 32));
    o2[(size_t)(2*p)*131072 + m2]   = v0;
    o2[(size_t)(2*p+1)*131072 + m2] = v1;
  }
}

// ---------------- launcher (12 launches total) ----------------
extern "C" void kernel_launch(void* const* d_in, const int* in_sizes, int n_in,
                              void* d_out, int out_size)
{
  (void)in_sizes; (void)n_in; (void)out_size;
  const float* x     = (const float*)d_in[0];
  const float* w_enc = (const float*)d_in[1];
  const float* b_enc = (const float*)d_in[2];
  const float* wq    = (const float*)d_in[3];
  const float* bq    = (const float*)d_in[4];
  const float* wk    = (const float*)d_in[5];
  const float* bk    = (const float*)d_in[6];
  const float* wv    = (const float*)d_in[7];
  const float* bv    = (const float*)d_in[8];
  const float* W_ii  = (const float*)d_in[9];
  const float* W_ig  = (const float*)d_in[13];
  const float* W_io  = (const float*)d_in[15];
  const float* w_fc  = (const float*)d_in[17];
  const float* b_fc  = (const float*)d_in[18];
  const float* w_d1  = (const float*)d_in[19];
  const float* b_d1  = (const float*)d_in[20];
  const float* w_d2  = (const float*)d_in[21];
  const float* b_d2  = (const float*)d_in[22];
  const float* w_d3  = (const float*)d_in[23];
  const float* b_d3  = (const float*)d_in[24];

  float* outp = (float*)d_out;
  float* xhat = outp;                  // [16,64,32,128] = 4194304
  float* z1   = outp + 4194304;        // [16,128]
  float* z2   = z1 + 2048;             // [16,128]
  float* kl1  = z2 + 2048;             // scalar
  float* kl2  = kl1 + 1;               // scalar

  // -------- pass 1: encode(x, key=1) --------
  headsF_kernel<<<256, 256>>>(x, w_enc, b_enc, wq, bq, wk, bk, wv, bv);
  attn_kernel<<<256, 256>>>();
  gatesC_kernel<<<192, 256>>>(W_ii, W_ig, W_io);
  rlf_kernel<<<16, 256>>>(w_fc, b_fc);
  kl_kernel<<<1, 256>>>(1u, z1, kl1);
  // -------- decode(z1) --------
  dec_small_kernel<<<1, 256>>>(z1, w_d1, b_d1, w_d2, b_d2);
  big_kernel<<<512, 256>>>(w_d3, b_d3, xhat);
  // -------- pass 2: encode(x_hat1, key=2) --------
  headsF_kernel<<<256, 256>>>(xhat, w_enc, b_enc, wq, bq, wk, bk, wv, bv);
  attn_kernel<<<256, 256>>>();
  gatesC_kernel<<<192, 256>>>(W_ii, W_ig, W_io);
  rlf_kernel<<<16, 256>>>(w_fc, b_fc);
  kl_kernel<<<1, 256>>>(2u, z2, kl2);
}

// round 10
// speedup vs baseline: 1.1364x; 1.1364x over previous
#include <cuda_runtime.h>
#include <math.h>

// Problem dims
#define BB_ 16
#define T_ 64
#define S_ 32
#define F_ 128
#define H_ 128
#define NH_ 4

// ---------------- scratch (no allocations allowed) ----------------
__device__ float g_q[BB_*NH_*H_*S_];     // 262144
__device__ float g_k[BB_*NH_*H_*S_];
__device__ float g_v[BB_*NH_*H_*S_];
__device__ float g_att4[BB_*NH_*H_*S_];
__device__ float g_part[3*32*BB_*H_];    // 196608  gate split-K partials
__device__ float g_fc[BB_*2*H_];         // 4096    fc out (mu|logvar)
__device__ float g_h2[BB_*H_];           // 2048    decoder h2

// grid-barrier state (sense-reversing via generation counter)
__device__ unsigned int g_cnt = 0;
__device__ unsigned int g_gen = 0;

__device__ __forceinline__ void grid_barrier(int nb){
  __syncthreads();
  if (threadIdx.x == 0) {
    __threadfence();
    unsigned int gen = *((volatile unsigned int*)&g_gen);
    unsigned int old = atomicAdd(&g_cnt, 1u);
    if (old == (unsigned int)nb - 1u) {
      *((volatile unsigned int*)&g_cnt) = 0u;
      __threadfence();
      atomicAdd(&g_gen, 1u);
    } else {
      while (*((volatile unsigned int*)&g_gen) == gen) { }
    }
    __threadfence();
  }
  __syncthreads();
}

__device__ __forceinline__ unsigned int rotl32_(unsigned int v, int d){ return (v << d) | (v >> (32 - d)); }

// Neumaier compensated accumulate: s += p with running compensation c.
__device__ __forceinline__ void kadd_(float& s, float& c, float p){
  float t = s + p;
  c += (fabsf(s) >= fabsf(p)) ? ((s - t) + p) : ((p - t) + s);
  s = t;
}

// Exact JAX threefry2x32 (20 rounds), key = (k0, k1)
__device__ __forceinline__ void threefry2x32_(unsigned int k0, unsigned int k1,
    unsigned int c0, unsigned int c1, unsigned int& o0, unsigned int& o1)
{
  unsigned int ks2 = k0 ^ k1 ^ 0x1BD11BDAu;
  unsigned int x0 = c0 + k0, x1 = c1 + k1;
  const int ra[4] = {13,15,26,6};
  const int rb[4] = {17,29,16,24};
  #pragma unroll
  for (int i=0;i<4;i++){ x0 += x1; x1 = rotl32_(x1, ra[i]); x1 ^= x0; }
  x0 += k1; x1 += ks2 + 1u;
  #pragma unroll
  for (int i=0;i<4;i++){ x0 += x1; x1 = rotl32_(x1, rb[i]); x1 ^= x0; }
  x0 += ks2; x1 += k0 + 2u;
  #pragma unroll
  for (int i=0;i<4;i++){ x0 += x1; x1 = rotl32_(x1, ra[i]); x1 ^= x0; }
  x0 += k0; x1 += k1 + 3u;
  #pragma unroll
  for (int i=0;i<4;i++){ x0 += x1; x1 = rotl32_(x1, rb[i]); x1 ^= x0; }
  x0 += k1; x1 += ks2 + 4u;
  #pragma unroll
  for (int i=0;i<4;i++){ x0 += x1; x1 = rotl32_(x1, ra[i]); x1 ^= x0; }
  x0 += ks2; x1 += k0 + 5u;
  o0 = x0; o1 = x1;
}

// ---------------- fused encoder pass: heads -> attn -> gates -> rlf -> kl (+dec) ----
// grid MUST be 128 blocks (single wave, co-resident) for the grid barrier.
#define NB_ 128

__global__ void __launch_bounds__(256) enc_kernel(
    const float* __restrict__ xsrc,
    const float* __restrict__ w_enc, const float* __restrict__ b_enc,
    const float* __restrict__ wq, const float* __restrict__ bq,
    const float* __restrict__ wk, const float* __restrict__ bk,
    const float* __restrict__ wv, const float* __restrict__ bv,
    const float* __restrict__ Wii, const float* __restrict__ Wig, const float* __restrict__ Wio,
    const float* __restrict__ w_fc, const float* __restrict__ b_fc,
    unsigned int keylo, float* __restrict__ z_out, float* __restrict__ kl_out,
    int do_dec,
    const float* __restrict__ w_d1, const float* __restrict__ b_d1,
    const float* __restrict__ w_d2, const float* __restrict__ b_d2)
{
  __shared__ __align__(16) float pool[10528];   // 42112 B, unioned across stages
  int blk = blockIdx.x, tid = threadIdx.x;

  // ================= stage A: fused hid + q/k/v head projections =================
  {
    float* xs  = pool;            // 32*129
    float* hsm = pool + 4128;     // 32*33
    float* wqn = pool + 5184;     // 32*33
    float* wkn = pool + 6240;
    float* wvn = pool + 7296;
    for (int u = blk; u < 256; u += NB_) {
      int b = u >> 4, n = (u >> 2) & 3, ht = u & 3;
      const float* xb = xsrc + (size_t)b*(T_*S_*F_) + (size_t)(T_-1)*(S_*F_);
      for (int i = tid; i < S_*F_; i += 256) {
        int s = i >> 7, f = i & 127;
        xs[s*129+f] = xb[i];
      }
      for (int i = tid; i < S_*S_; i += 256) {
        int sp = i >> 5, s = i & 31;
        wqn[sp*33+s] = wq[sp*(S_*NH_) + n*S_ + s];
        wkn[sp*33+s] = wk[sp*(S_*NH_) + n*S_ + s];
        wvn[sp*33+s] = wv[sp*(S_*NH_) + n*S_ + s];
      }
      __syncthreads();
      for (int i = tid; i < 32*S_; i += 256) {
        int hl = i >> 5, s = i & 31;
        int h = ht*32 + hl;
        float acc = 0.f, cc = 0.f;
        #pragma unroll 8
        for (int f = 0; f < F_; f++)
          kadd_(acc, cc, xs[s*129+f] * w_enc[f*H_ + h]);
        hsm[hl*33+s] = (acc + cc) + b_enc[h];
      }
      __syncthreads();
      const float scale = 0.08838834764831845f; // 1/sqrt(H)
      size_t base = ((size_t)(b*NH_ + n))*(H_*S_);
      for (int i = tid; i < 32*S_; i += 256) {
        int hl = i >> 5, s = i & 31;
        float aq = 0.f, cq = 0.f, ak = 0.f, ck = 0.f, av = 0.f, cv = 0.f;
        #pragma unroll
        for (int sp = 0; sp < S_; sp++) {
          float hv = hsm[hl*33+sp];
          kadd_(aq, cq, hv * wqn[sp*33+s]);
          kadd_(ak, ck, hv * wkn[sp*33+s]);
          kadd_(av, cv, hv * wvn[sp*33+s]);
        }
        size_t o = base + (size_t)(ht*32+hl)*S_ + s;
        g_q[o] = ((aq + cq) + bq[n*S_+s]) * scale;
        g_k[o] = (ak + ck) + bk[n*S_+s];
        g_v[o] = (av + cv) + bv[n*S_+s];
      }
      __syncthreads();
    }
  }
  grid_barrier(NB_);

  // ================= stage B: attention =================
  {
    float* ksm  = pool;          // 128*33
    float* vsm  = pool + 4224;   // 128*33
    float* qsm  = pool + 8448;   // 32*33
    float* prob = pool + 9504;   // 8*128
    for (int u = blk; u < 256; u += NB_) {
      int bn = u >> 2, hq = u & 3;
      size_t base = (size_t)bn * (H_*S_);
      for (int i = tid; i < H_*S_; i += 256) {
        ksm[(i>>5)*33 + (i&31)] = g_k[base + i];
        vsm[(i>>5)*33 + (i&31)] = g_v[base + i];
      }
      for (int i = tid; i < 32*S_; i += 256) {
        qsm[(i>>5)*33 + (i&31)] = g_q[base + (size_t)hq*32*S_ + i];
      }
      __syncthreads();
      int warp = tid >> 5, lane = tid & 31;
      float* pw = prob + warp*128;
      #pragma unroll
      for (int r = 0; r < 4; r++) {
        int hh = warp*4 + r;
        float lg[4];
        #pragma unroll
        for (int j = 0; j < 4; j++) {
          int g = lane + 32*j;
          float acc = 0.f, cc = 0.f;
          #pragma unroll
          for (int s = 0; s < S_; s++)
            kadd_(acc, cc, qsm[hh*33+s] * ksm[g*33+s]);
          lg[j] = acc + cc;
        }
        float m = fmaxf(fmaxf(lg[0],lg[1]), fmaxf(lg[2],lg[3]));
        #pragma unroll
        for (int o = 16; o; o >>= 1) m = fmaxf(m, __shfl_xor_sync(0xffffffffu, m, o));
        float ssum = 0.f;
        #pragma unroll
        for (int j = 0; j < 4; j++){ lg[j] = expf(lg[j]-m); ssum += lg[j]; }
        #pragma unroll
        for (int o = 16; o; o >>= 1) ssum += __shfl_xor_sync(0xffffffffu, ssum, o);
        float inv = 1.f/ssum;
        #pragma unroll
        for (int j = 0; j < 4; j++) pw[lane + 32*j] = lg[j]*inv;
        __syncwarp();
        float acc = 0.f, cc = 0.f;
        #pragma unroll 8
        for (int g = 0; g < H_; g++)
          kadd_(acc, cc, pw[g] * vsm[g*33+lane]);
        g_att4[base + (size_t)(hq*32+hh)*S_ + lane] = acc + cc;
        __syncwarp();
      }
      __syncthreads();
    }
  }
  grid_barrier(NB_);

  // ================= stage C: gate GEMM with fused head-mean+ReLU =================
  {
    float* as = pool;   // 8*128
    for (int u = blk; u < 192; u += NB_) {
      int gate = u / 64;
      int rem  = u - gate*64;
      int chunk = rem >> 1, bh = rem & 1;
      const float* Wm = (gate == 0) ? Wii : (gate == 1) ? Wig : Wio;
      int j0 = chunk*128;
      for (int i = tid; i < 8*128; i += 256) {
        int bb = i >> 7, j = i & 127;
        int bg = bh*8 + bb;
        size_t bbase = (size_t)bg*4*(H_*S_);
        int hs = j0 + j;
        float v = (g_att4[bbase + hs] + g_att4[bbase + 4096 + hs])
                + (g_att4[bbase + 8192 + hs] + g_att4[bbase + 12288 + hs]);
        v *= 0.25f;
        as[i] = v > 0.f ? v : 0.f;
      }
      __syncthreads();
      int m = tid & 127, half = tid >> 7;
      float acc[4] = {0.f,0.f,0.f,0.f};
      float cmp[4] = {0.f,0.f,0.f,0.f};
      #pragma unroll 2
      for (int j = 0; j < 128; j++) {
        float w = Wm[(size_t)(j0+j)*H_ + m];
        #pragma unroll
        for (int bb = 0; bb < 4; bb++)
          kadd_(acc[bb], cmp[bb], as[(half*4+bb)*128 + j] * w);
      }
      size_t cbase = ((size_t)(gate*32 + chunk))*(BB_*H_);
      #pragma unroll
      for (int bb = 0; bb < 4; bb++)
        g_part[cbase + (bh*8 + half*4 + bb)*H_ + m] = acc[bb] + cmp[bb];
      __syncthreads();
    }
  }
  grid_barrier(NB_);

  // ================= stage D: reduce + LSTM + fc (one unit per batch row) =========
  {
    float* s_g = pool;         // 384
    float* s_h = pool + 384;   // 128
    if (blk < 16) {
      int b = blk;
      for (int idx = tid; idx < 384; idx += 256) {
        int gate = idx >> 7, m = idx & 127;
        int r = b*128 + m;
        float s = 0.f, c = 0.f;
        #pragma unroll
        for (int ch = 0; ch < 32; ch++)
          kadd_(s, c, g_part[(size_t)(gate*32 + ch)*(BB_*H_) + r]);
        s_g[gate*128 + m] = s + c;
      }
      __syncthreads();
      if (tid < 128) {
        double iv = 1.0/(1.0 + exp(-(double)s_g[tid]));
        double gv = tanh((double)s_g[128 + tid]);
        double ov = 1.0/(1.0 + exp(-(double)s_g[256 + tid]));
        s_h[tid] = (float)(ov * tanh(iv * gv));
      }
      __syncthreads();
      int c = tid;   // < 256
      float s = 0.f, cc = 0.f;
      #pragma unroll 8
      for (int mm = 0; mm < 128; mm++)
        kadd_(s, cc, s_h[mm] * w_fc[mm*256 + c]);
      g_fc[b*256 + c] = (s + cc) + b_fc[c];
    }
  }
  grid_barrier(NB_);

  // ================= stage E: reparam + KL (+ decode MLP), block 0 only ===========
  if (blk == 0) {
    float* s_z   = pool + 4096;                 // 2048
    double* redd = (double*)(pool + 6144);      // 256 doubles
    double kacc = 0.0;
    for (int idx = tid; idx < 2048; idx += 256) {
      int bb = idx >> 7, k = idx & 127;
      float mu = g_fc[bb*256 + k];
      float lv = g_fc[bb*256 + 128 + k];
      unsigned int o0, o1;
      threefry2x32_(0u, keylo, 0u, (unsigned int)idx, o0, o1);
      unsigned int bits = o0 ^ o1;
      float f = __uint_as_float((bits >> 9) | 0x3f800000u) - 1.0f;   // [0,1)
      const float lo = -0.99999994f;                                 // nextafter(-1,0)
      float u = fmaxf(lo, fmaf(f, 2.0f, lo));
      float eps = 1.4142135623730951f * erfinvf(u);
      float zv = fmaf(eps, expf(0.5f*lv), mu);
      z_out[idx] = zv;
      s_z[idx] = zv;
      double dmu = (double)mu, dlv = (double)lv;
      kacc += 1.0 + dlv - dmu*dmu - exp(dlv);
    }
    redd[tid] = kacc;
    __syncthreads();
    for (int o = 128; o; o >>= 1) {
      if (tid < o) redd[tid] += redd[tid + o];
      __syncthreads();
    }
    if (tid == 0) kl_out[0] = (float)(-0.5 * redd[0] * (1.0/2048.0));
    if (do_dec) {
      float* h1 = pool;   // 2048 (does not overlap s_z)
      __syncthreads();
      for (int i = tid; i < 2048; i += 256) {
        int bb = i >> 7, c = i & 127;
        float s = 0.f, cc = 0.f;
        #pragma unroll 8
        for (int j = 0; j < 128; j++)
          kadd_(s, cc, s_z[bb*128+j] * w_d1[j*128+c]);
        float acc = (s + cc) + b_d1[c];
        h1[i] = fmaxf(acc, 0.f);
      }
      __syncthreads();
      for (int i = tid; i < 2048; i += 256) {
        int bb = i >> 7, c = i & 127;
        float s = 0.f, cc = 0.f;
        #pragma unroll 8
        for (int j = 0; j < 128; j++)
          kadd_(s, cc, h1[bb*128+j] * w_d2[j*128+c]);
        float acc = (s + cc) + b_d2[c];
        g_h2[i] = fmaxf(acc, 0.f);
      }
    }
  }
}

// ---------------- big decode GEMM h2[16,128] @ w_d3[128,262144] + b_d3 ----------------
// Memory-bound (134 MB of w_d3). Batch pairs packed into f32x2 so the FMA pipe
// keeps up with HBM (dual-FP32 fma.rn.f32x2).
__device__ __forceinline__ unsigned long long pk2_(float a, float b){
  return (unsigned long long)__float_as_uint(a) | ((unsigned long long)__float_as_uint(b) << 32);
}

__global__ void __launch_bounds__(256) big_kernel(
    const float* __restrict__ w_d3, const float* __restrict__ b_d3, float* __restrict__ out)
{
  __shared__ unsigned long long hp[8*128];   // (b-pair, j) packed h2 values
  int tid = threadIdx.x;
  for (int i = tid; i < 1024; i += 256) {
    int p = i >> 7, j = i & 127;
    hp[i] = pk2_(g_h2[(2*p)*128 + j], g_h2[(2*p+1)*128 + j]);
  }
  __syncthreads();
  size_t m2 = (size_t)blockIdx.x*256 + tid;    // float2 column index, < 131072
  const float2* w2 = (const float2*)w_d3;
  float2 bv2 = ((const float2*)b_d3)[m2];
  unsigned long long accx[8], accy[8];
  unsigned long long bx = pk2_(bv2.x, bv2.x), by = pk2_(bv2.y, bv2.y);
  #pragma unroll
  for (int p = 0; p < 8; p++){ accx[p] = bx; accy[p] = by; }
  #pragma unroll 4
  for (int j = 0; j < 128; j++) {
    float2 w = __ldg(&w2[(size_t)j*131072 + m2]);
    unsigned long long wx = pk2_(w.x, w.x), wy = pk2_(w.y, w.y);
    #pragma unroll
    for (int p = 0; p < 8; p++) {
      unsigned long long hpair = hp[p*128 + j];
      asm("fma.rn.f32x2 %0, %1, %2, %3;" : "=l"(accx[p]) : "l"(hpair), "l"(wx), "l"(accx[p]));
      asm("fma.rn.f32x2 %0, %1, %2, %3;" : "=l"(accy[p]) : "l"(hpair), "l"(wy), "l"(accy[p]));
    }
  }
  float2* o2 = (float2*)out;
  #pragma unroll
  for (int p = 0; p < 8; p++) {
    float2 v0, v1;
    v0.x = __uint_as_float((unsigned int)accx[p]);
    v0.y = __uint_as_float((unsigned int)accy[p]);
    v1.x = __uint_as_float((unsigned int)(accx[p] >> 32));
    v1.y = __uint_as_float((unsigned int)(accy[p] >> 32));
    o2[(size_t)(2*p)*131072 + m2]   = v0;
    o2[(size_t)(2*p+1)*131072 + m2] = v1;
  }
}

// ---------------- launcher (3 launches total) ----------------
extern "C" void kernel_launch(void* const* d_in, const int* in_sizes, int n_in,
                              void* d_out, int out_size)
{
  (void)in_sizes; (void)n_in; (void)out_size;
  const float* x     = (const float*)d_in[0];
  const float* w_enc = (const float*)d_in[1];
  const float* b_enc = (const float*)d_in[2];
  const float* wq    = (const float*)d_in[3];
  const float* bq    = (const float*)d_in[4];
  const float* wk    = (const float*)d_in[5];
  const float* bk    = (const float*)d_in[6];
  const float* wv    = (const float*)d_in[7];
  const float* bv    = (const float*)d_in[8];
  const float* W_ii  = (const float*)d_in[9];
  const float* W_ig  = (const float*)d_in[13];
  const float* W_io  = (const float*)d_in[15];
  const float* w_fc  = (const float*)d_in[17];
  const float* b_fc  = (const float*)d_in[18];
  const float* w_d1  = (const float*)d_in[19];
  const float* b_d1  = (const float*)d_in[20];
  const float* w_d2  = (const float*)d_in[21];
  const float* b_d2  = (const float*)d_in[22];
  const float* w_d3  = (const float*)d_in[23];
  const float* b_d3  = (const float*)d_in[24];

  float* outp = (float*)d_out;
  float* xhat = outp;                  // [16,64,32,128] = 4194304
  float* z1   = outp + 4194304;        // [16,128]
  float* z2   = z1 + 2048;             // [16,128]
  float* kl1  = z2 + 2048;             // scalar
  float* kl2  = kl1 + 1;               // scalar

  // -------- pass 1: encode(x, key=1) + decode MLP --------
  enc_kernel<<<NB_, 256>>>(x, w_enc, b_enc, wq, bq, wk, bk, wv, bv,
                           W_ii, W_ig, W_io, w_fc, b_fc,
                           1u, z1, kl1, 1, w_d1, b_d1, w_d2, b_d2);
  // -------- big decode GEMM --------
  big_kernel<<<512, 256>>>(w_d3, b_d3, xhat);
  // -------- pass 2: encode(x_hat1, key=2) --------
  enc_kernel<<<NB_, 256>>>(xhat, w_enc, b_enc, wq, bq, wk, bk, wv, bv,
                           W_ii, W_ig, W_io, w_fc, b_fc,
                           2u, z2, kl2, 0, w_d1, b_d1, w_d2, b_d2);
}

// round 11
// speedup vs baseline: 1.7384x; 1.5298x over previous
#include <cuda_runtime.h>
#include <math.h>

// Problem dims
#define BB_ 16
#define T_ 64
#define S_ 32
#define F_ 128
#define H_ 128
#define NH_ 4

// ---------------- scratch (no allocations allowed) ----------------
__device__ float g_q[BB_*NH_*H_*S_];     // 262144
__device__ float g_k[BB_*NH_*H_*S_];
__device__ float g_v[BB_*NH_*H_*S_];
__device__ float g_att4[BB_*NH_*H_*S_];
__device__ float g_part[3*32*BB_*H_];    // 196608  gate split-K partials
__device__ float g_fc[BB_*2*H_];         // 4096    fc out (mu|logvar)
__device__ float g_h2[BB_*H_];           // 2048    decoder h2

// grid-barrier state (sense-reversing via generation counter)
__device__ unsigned int g_cnt = 0;
__device__ unsigned int g_gen = 0;

__device__ __forceinline__ void grid_barrier(int nb){
  __syncthreads();
  if (threadIdx.x == 0) {
    __threadfence();
    unsigned int gen = *((volatile unsigned int*)&g_gen);
    unsigned int old = atomicAdd(&g_cnt, 1u);
    if (old == (unsigned int)nb - 1u) {
      *((volatile unsigned int*)&g_cnt) = 0u;
      __threadfence();
      atomicAdd(&g_gen, 1u);
    } else {
      while (*((volatile unsigned int*)&g_gen) == gen) { }
    }
    __threadfence();
  }
  __syncthreads();
}

__device__ __forceinline__ unsigned int rotl32_(unsigned int v, int d){ return (v << d) | (v >> (32 - d)); }

// Neumaier compensated accumulate (kept only in cheap, KL-sensitive spots).
__device__ __forceinline__ void kadd_(float& s, float& c, float p){
  float t = s + p;
  c += (fabsf(s) >= fabsf(p)) ? ((s - t) + p) : ((p - t) + s);
  s = t;
}

// Exact JAX threefry2x32 (20 rounds), key = (k0, k1)
__device__ __forceinline__ void threefry2x32_(unsigned int k0, unsigned int k1,
    unsigned int c0, unsigned int c1, unsigned int& o0, unsigned int& o1)
{
  unsigned int ks2 = k0 ^ k1 ^ 0x1BD11BDAu;
  unsigned int x0 = c0 + k0, x1 = c1 + k1;
  const int ra[4] = {13,15,26,6};
  const int rb[4] = {17,29,16,24};
  #pragma unroll
  for (int i=0;i<4;i++){ x0 += x1; x1 = rotl32_(x1, ra[i]); x1 ^= x0; }
  x0 += k1; x1 += ks2 + 1u;
  #pragma unroll
  for (int i=0;i<4;i++){ x0 += x1; x1 = rotl32_(x1, rb[i]); x1 ^= x0; }
  x0 += ks2; x1 += k0 + 2u;
  #pragma unroll
  for (int i=0;i<4;i++){ x0 += x1; x1 = rotl32_(x1, ra[i]); x1 ^= x0; }
  x0 += k0; x1 += k1 + 3u;
  #pragma unroll
  for (int i=0;i<4;i++){ x0 += x1; x1 = rotl32_(x1, rb[i]); x1 ^= x0; }
  x0 += k1; x1 += ks2 + 4u;
  #pragma unroll
  for (int i=0;i<4;i++){ x0 += x1; x1 = rotl32_(x1, ra[i]); x1 ^= x0; }
  x0 += ks2; x1 += k0 + 5u;
  o0 = x0; o1 = x1;
}

// ---------------- fused encoder pass: heads -> attn -> gates -> rlf -> kl (+dec) ----
// grid MUST be 128 blocks (single wave, co-resident) for the grid barrier.
#define NB_ 128

__global__ void __launch_bounds__(256) enc_kernel(
    const float* __restrict__ xsrc,
    const float* __restrict__ w_enc, const float* __restrict__ b_enc,
    const float* __restrict__ wq, const float* __restrict__ bq,
    const float* __restrict__ wk, const float* __restrict__ bk,
    const float* __restrict__ wv, const float* __restrict__ bv,
    const float* __restrict__ Wii, const float* __restrict__ Wig, const float* __restrict__ Wio,
    const float* __restrict__ w_fc, const float* __restrict__ b_fc,
    unsigned int keylo, float* __restrict__ z_out, float* __restrict__ kl_out,
    int do_dec,
    const float* __restrict__ w_d1, const float* __restrict__ b_d1,
    const float* __restrict__ w_d2, const float* __restrict__ b_d2)
{
  __shared__ __align__(16) float pool[10528];   // 42112 B, unioned across stages
  int blk = blockIdx.x, tid = threadIdx.x;

  // ================= stage A: fused hid + q/k/v head projections =================
  // 8-partial blocked tree accumulation (error ~20 eps vs 128 eps sequential).
  {
    float* xs  = pool;            // 32*129
    float* hsm = pool + 4128;     // 32*33
    float* wqn = pool + 5184;     // 32*33
    float* wkn = pool + 6240;
    float* wvn = pool + 7296;
    for (int u = blk; u < 256; u += NB_) {
      int b = u >> 4, n = (u >> 2) & 3, ht = u & 3;
      const float* xb = xsrc + (size_t)b*(T_*S_*F_) + (size_t)(T_-1)*(S_*F_);
      for (int i = tid; i < S_*F_; i += 256) {
        int s = i >> 7, f = i & 127;
        xs[s*129+f] = xb[i];
      }
      for (int i = tid; i < S_*S_; i += 256) {
        int sp = i >> 5, s = i & 31;
        wqn[sp*33+s] = wq[sp*(S_*NH_) + n*S_ + s];
        wkn[sp*33+s] = wk[sp*(S_*NH_) + n*S_ + s];
        wvn[sp*33+s] = wv[sp*(S_*NH_) + n*S_ + s];
      }
      __syncthreads();
      for (int i = tid; i < 32*S_; i += 256) {
        int hl = i >> 5, s = i & 31;
        int h = ht*32 + hl;
        float p[8] = {0.f,0.f,0.f,0.f,0.f,0.f,0.f,0.f};
        #pragma unroll
        for (int fb = 0; fb < 8; fb++)
          #pragma unroll
          for (int f0 = 0; f0 < 16; f0++) {
            int f = fb*16 + f0;
            p[fb] = fmaf(xs[s*129+f], w_enc[f*H_ + h], p[fb]);
          }
        float acc = ((p[0]+p[1])+(p[2]+p[3])) + ((p[4]+p[5])+(p[6]+p[7]));
        hsm[hl*33+s] = acc + b_enc[h];
      }
      __syncthreads();
      const float scale = 0.08838834764831845f; // 1/sqrt(H)
      size_t base = ((size_t)(b*NH_ + n))*(H_*S_);
      for (int i = tid; i < 32*S_; i += 256) {
        int hl = i >> 5, s = i & 31;
        float pq[4] = {0.f,0.f,0.f,0.f};
        float pk[4] = {0.f,0.f,0.f,0.f};
        float pv[4] = {0.f,0.f,0.f,0.f};
        #pragma unroll
        for (int sb = 0; sb < 4; sb++)
          #pragma unroll
          for (int s0 = 0; s0 < 8; s0++) {
            int sp = sb*8 + s0;
            float hv = hsm[hl*33+sp];
            pq[sb] = fmaf(hv, wqn[sp*33+s], pq[sb]);
            pk[sb] = fmaf(hv, wkn[sp*33+s], pk[sb]);
            pv[sb] = fmaf(hv, wvn[sp*33+s], pv[sb]);
          }
        float aq = (pq[0]+pq[1]) + (pq[2]+pq[3]);
        float ak = (pk[0]+pk[1]) + (pk[2]+pk[3]);
        float av = (pv[0]+pv[1]) + (pv[2]+pv[3]);
        size_t o = base + (size_t)(ht*32+hl)*S_ + s;
        g_q[o] = (aq + bq[n*S_+s]) * scale;
        g_k[o] = ak + bk[n*S_+s];
        g_v[o] = av + bv[n*S_+s];
      }
      __syncthreads();
    }
  }
  grid_barrier(NB_);

  // ================= stage B: attention =================
  {
    float* ksm  = pool;          // 128*33
    float* vsm  = pool + 4224;   // 128*33
    float* qsm  = pool + 8448;   // 32*33
    float* prob = pool + 9504;   // 8*128
    for (int u = blk; u < 256; u += NB_) {
      int bn = u >> 2, hq = u & 3;
      size_t base = (size_t)bn * (H_*S_);
      for (int i = tid; i < H_*S_; i += 256) {
        ksm[(i>>5)*33 + (i&31)] = g_k[base + i];
        vsm[(i>>5)*33 + (i&31)] = g_v[base + i];
      }
      for (int i = tid; i < 32*S_; i += 256) {
        qsm[(i>>5)*33 + (i&31)] = g_q[base + (size_t)hq*32*S_ + i];
      }
      __syncthreads();
      int warp = tid >> 5, lane = tid & 31;
      float* pw = prob + warp*128;
      #pragma unroll
      for (int r = 0; r < 4; r++) {
        int hh = warp*4 + r;
        float lg[4];
        #pragma unroll
        for (int j = 0; j < 4; j++) {
          int g = lane + 32*j;
          float pp[4] = {0.f,0.f,0.f,0.f};
          #pragma unroll
          for (int sb = 0; sb < 4; sb++)
            #pragma unroll
            for (int s0 = 0; s0 < 8; s0++) {
              int s = sb*8 + s0;
              pp[sb] = fmaf(qsm[hh*33+s], ksm[g*33+s], pp[sb]);
            }
          lg[j] = (pp[0]+pp[1]) + (pp[2]+pp[3]);
        }
        float m = fmaxf(fmaxf(lg[0],lg[1]), fmaxf(lg[2],lg[3]));
        #pragma unroll
        for (int o = 16; o; o >>= 1) m = fmaxf(m, __shfl_xor_sync(0xffffffffu, m, o));
        float ssum = 0.f;
        #pragma unroll
        for (int j = 0; j < 4; j++){ lg[j] = expf(lg[j]-m); ssum += lg[j]; }
        #pragma unroll
        for (int o = 16; o; o >>= 1) ssum += __shfl_xor_sync(0xffffffffu, ssum, o);
        float inv = 1.f/ssum;
        #pragma unroll
        for (int j = 0; j < 4; j++) pw[lane + 32*j] = lg[j]*inv;
        __syncwarp();
        float pp[8] = {0.f,0.f,0.f,0.f,0.f,0.f,0.f,0.f};
        #pragma unroll
        for (int gb = 0; gb < 8; gb++)
          #pragma unroll
          for (int g0 = 0; g0 < 16; g0++) {
            int g = gb*16 + g0;
            pp[gb] = fmaf(pw[g], vsm[g*33+lane], pp[gb]);
          }
        float acc = ((pp[0]+pp[1])+(pp[2]+pp[3])) + ((pp[4]+pp[5])+(pp[6]+pp[7]));
        g_att4[base + (size_t)(hq*32+hh)*S_ + lane] = acc;
        __syncwarp();
      }
      __syncthreads();
    }
  }
  grid_barrier(NB_);

  // ================= stage C: gate GEMM with fused head-mean+ReLU =================
  // 4 partials of 32 within each K=128 chunk; chunks Kahan-combined in stage D.
  {
    float* as = pool;   // 8*128
    for (int u = blk; u < 192; u += NB_) {
      int gate = u / 64;
      int rem  = u - gate*64;
      int chunk = rem >> 1, bh = rem & 1;
      const float* Wm = (gate == 0) ? Wii : (gate == 1) ? Wig : Wio;
      int j0 = chunk*128;
      for (int i = tid; i < 8*128; i += 256) {
        int bb = i >> 7, j = i & 127;
        int bg = bh*8 + bb;
        size_t bbase = (size_t)bg*4*(H_*S_);
        int hs = j0 + j;
        float v = (g_att4[bbase + hs] + g_att4[bbase + 4096 + hs])
                + (g_att4[bbase + 8192 + hs] + g_att4[bbase + 12288 + hs]);
        v *= 0.25f;
        as[i] = v > 0.f ? v : 0.f;
      }
      __syncthreads();
      int m = tid & 127, half = tid >> 7;
      float acc[4][4];
      #pragma unroll
      for (int bb = 0; bb < 4; bb++)
        #pragma unroll
        for (int jb = 0; jb < 4; jb++) acc[bb][jb] = 0.f;
      #pragma unroll
      for (int jb = 0; jb < 4; jb++)
        #pragma unroll 8
        for (int j0i = 0; j0i < 32; j0i++) {
          int j = jb*32 + j0i;
          float w = Wm[(size_t)(j0+j)*H_ + m];
          #pragma unroll
          for (int bb = 0; bb < 4; bb++)
            acc[bb][jb] = fmaf(as[(half*4+bb)*128 + j], w, acc[bb][jb]);
        }
      size_t cbase = ((size_t)(gate*32 + chunk))*(BB_*H_);
      #pragma unroll
      for (int bb = 0; bb < 4; bb++)
        g_part[cbase + (bh*8 + half*4 + bb)*H_ + m] =
          (acc[bb][0]+acc[bb][1]) + (acc[bb][2]+acc[bb][3]);
      __syncthreads();
    }
  }
  grid_barrier(NB_);

  // ================= stage D: reduce + LSTM + fc (one unit per batch row) =========
  // Kahan across chunks + double LSTM + Kahan fc — cheap and KL-critical.
  {
    float* s_g = pool;         // 384
    float* s_h = pool + 384;   // 128
    if (blk < 16) {
      int b = blk;
      for (int idx = tid; idx < 384; idx += 256) {
        int gate = idx >> 7, m = idx & 127;
        int r = b*128 + m;
        float s = 0.f, c = 0.f;
        #pragma unroll
        for (int ch = 0; ch < 32; ch++)
          kadd_(s, c, g_part[(size_t)(gate*32 + ch)*(BB_*H_) + r]);
        s_g[gate*128 + m] = s + c;
      }
      __syncthreads();
      if (tid < 128) {
        double iv = 1.0/(1.0 + exp(-(double)s_g[tid]));
        double gv = tanh((double)s_g[128 + tid]);
        double ov = 1.0/(1.0 + exp(-(double)s_g[256 + tid]));
        s_h[tid] = (float)(ov * tanh(iv * gv));
      }
      __syncthreads();
      int c = tid;   // < 256
      float s = 0.f, cc = 0.f;
      #pragma unroll 8
      for (int mm = 0; mm < 128; mm++)
        kadd_(s, cc, s_h[mm] * w_fc[mm*256 + c]);
      g_fc[b*256 + c] = (s + cc) + b_fc[c];
    }
  }
  grid_barrier(NB_);

  // ================= stage E: reparam + KL (+ decode MLP), block 0 only ===========
  if (blk == 0) {
    float* s_z   = pool + 4096;                 // 2048
    double* redd = (double*)(pool + 6144);      // 256 doubles
    double kacc = 0.0;
    for (int idx = tid; idx < 2048; idx += 256) {
      int bb = idx >> 7, k = idx & 127;
      float mu = g_fc[bb*256 + k];
      float lv = g_fc[bb*256 + 128 + k];
      unsigned int o0, o1;
      threefry2x32_(0u, keylo, 0u, (unsigned int)idx, o0, o1);
      unsigned int bits = o0 ^ o1;
      float f = __uint_as_float((bits >> 9) | 0x3f800000u) - 1.0f;   // [0,1)
      const float lo = -0.99999994f;                                 // nextafter(-1,0)
      float u = fmaxf(lo, fmaf(f, 2.0f, lo));
      float eps = 1.4142135623730951f * erfinvf(u);
      float zv = fmaf(eps, expf(0.5f*lv), mu);
      z_out[idx] = zv;
      s_z[idx] = zv;
      double dmu = (double)mu, dlv = (double)lv;
      kacc += 1.0 + dlv - dmu*dmu - exp(dlv);
    }
    redd[tid] = kacc;
    __syncthreads();
    for (int o = 128; o; o >>= 1) {
      if (tid < o) redd[tid] += redd[tid + o];
      __syncthreads();
    }
    if (tid == 0) kl_out[0] = (float)(-0.5 * redd[0] * (1.0/2048.0));
    if (do_dec) {
      float* h1 = pool;   // 2048 (does not overlap s_z)
      __syncthreads();
      for (int i = tid; i < 2048; i += 256) {
        int bb = i >> 7, c = i & 127;
        float p[4] = {0.f,0.f,0.f,0.f};
        #pragma unroll
        for (int jb = 0; jb < 4; jb++)
          #pragma unroll 8
          for (int j0 = 0; j0 < 32; j0++) {
            int j = jb*32 + j0;
            p[jb] = fmaf(s_z[bb*128+j], w_d1[j*128+c], p[jb]);
          }
        float acc = ((p[0]+p[1]) + (p[2]+p[3])) + b_d1[c];
        h1[i] = fmaxf(acc, 0.f);
      }
      __syncthreads();
      for (int i = tid; i < 2048; i += 256) {
        int bb = i >> 7, c = i & 127;
        float p[4] = {0.f,0.f,0.f,0.f};
        #pragma unroll
        for (int jb = 0; jb < 4; jb++)
          #pragma unroll 8
          for (int j0 = 0; j0 < 32; j0++) {
            int j = jb*32 + j0;
            p[jb] = fmaf(h1[bb*128+j], w_d2[j*128+c], p[jb]);
          }
        float acc = ((p[0]+p[1]) + (p[2]+p[3])) + b_d2[c];
        g_h2[i] = fmaxf(acc, 0.f);
      }
    }
  }
}

// ---------------- big decode GEMM h2[16,128] @ w_d3[128,262144] + b_d3 ----------------
__device__ __forceinline__ unsigned long long pk2_(float a, float b){
  return (unsigned long long)__float_as_uint(a) | ((unsigned long long)__float_as_uint(b) << 32);
}

__global__ void __launch_bounds__(256) big_kernel(
    const float* __restrict__ w_d3, const float* __restrict__ b_d3, float* __restrict__ out)
{
  __shared__ unsigned long long hp[8*128];   // (b-pair, j) packed h2 values
  int tid = threadIdx.x;
  for (int i = tid; i < 1024; i += 256) {
    int p = i >> 7, j = i & 127;
    hp[i] = pk2_(g_h2[(2*p)*128 + j], g_h2[(2*p+1)*128 + j]);
  }
  __syncthreads();
  size_t m2 = (size_t)blockIdx.x*256 + tid;    // float2 column index, < 131072
  const float2* w2 = (const float2*)w_d3;
  float2 bv2 = ((const float2*)b_d3)[m2];
  unsigned long long accx[8], accy[8];
  unsigned long long bx = pk2_(bv2.x, bv2.x), by = pk2_(bv2.y, bv2.y);
  #pragma unroll
  for (int p = 0; p < 8; p++){ accx[p] = bx; accy[p] = by; }
  #pragma unroll 4
  for (int j = 0; j < 128; j++) {
    float2 w = __ldg(&w2[(size_t)j*131072 + m2]);
    unsigned long long wx = pk2_(w.x, w.x), wy = pk2_(w.y, w.y);
    #pragma unroll
    for (int p = 0; p < 8; p++) {
      unsigned long long hpair = hp[p*128 + j];
      asm("fma.rn.f32x2 %0, %1, %2, %3;" : "=l"(accx[p]) : "l"(hpair), "l"(wx), "l"(accx[p]));
      asm("fma.rn.f32x2 %0, %1, %2, %3;" : "=l"(accy[p]) : "l"(hpair), "l"(wy), "l"(accy[p]));
    }
  }
  float2* o2 = (float2*)out;
  #pragma unroll
  for (int p = 0; p < 8; p++) {
    float2 v0, v1;
    v0.x = __uint_as_float((unsigned int)accx[p]);
    v0.y = __uint_as_float((unsigned int)accy[p]);
    v1.x = __uint_as_float((unsigned int)(accx[p] >> 32));
    v1.y = __uint_as_float((unsigned int)(accy[p] >> 32));
    o2[(size_t)(2*p)*131072 + m2]   = v0;
    o2[(size_t)(2*p+1)*131072 + m2] = v1;
  }
}

// ---------------- launcher (3 launches total) ----------------
extern "C" void kernel_launch(void* const* d_in, const int* in_sizes, int n_in,
                              void* d_out, int out_size)
{
  (void)in_sizes; (void)n_in; (void)out_size;
  const float* x     = (const float*)d_in[0];
  const float* w_enc = (const float*)d_in[1];
  const float* b_enc = (const float*)d_in[2];
  const float* wq    = (const float*)d_in[3];
  const float* bq    = (const float*)d_in[4];
  const float* wk    = (const float*)d_in[5];
  const float* bk    = (const float*)d_in[6];
  const float* wv    = (const float*)d_in[7];
  const float* bv    = (const float*)d_in[8];
  const float* W_ii  = (const float*)d_in[9];
  const float* W_ig  = (const float*)d_in[13];
  const float* W_io  = (const float*)d_in[15];
  const float* w_fc  = (const float*)d_in[17];
  const float* b_fc  = (const float*)d_in[18];
  const float* w_d1  = (const float*)d_in[19];
  const float* b_d1  = (const float*)d_in[20];
  const float* w_d2  = (const float*)d_in[21];
  const float* b_d2  = (const float*)d_in[22];
  const float* w_d3  = (const float*)d_in[23];
  const float* b_d3  = (const float*)d_in[24];

  float* outp = (float*)d_out;
  float* xhat = outp;                  // [16,64,32,128] = 4194304
  float* z1   = outp + 4194304;        // [16,128]
  float* z2   = z1 + 2048;             // [16,128]
  float* kl1  = z2 + 2048;             // scalar
  float* kl2  = kl1 + 1;               // scalar

  // -------- pass 1: encode(x, key=1) + decode MLP --------
  enc_kernel<<<NB_, 256>>>(x, w_enc, b_enc, wq, bq, wk, bk, wv, bv,
                           W_ii, W_ig, W_io, w_fc, b_fc,
                           1u, z1, kl1, 1, w_d1, b_d1, w_d2, b_d2);
  // -------- big decode GEMM --------
  big_kernel<<<512, 256>>>(w_d3, b_d3, xhat);
  // -------- pass 2: encode(x_hat1, key=2) --------
  enc_kernel<<<NB_, 256>>>(xhat, w_enc, b_enc, wq, bq, wk, bk, wv, bv,
                           W_ii, W_ig, W_io, w_fc, b_fc,
                           2u, z2, kl2, 0, w_d1, b_d1, w_d2, b_d2);
}

// round 12
// speedup vs baseline: 1.8961x; 1.0907x over previous
#include <cuda_runtime.h>
#include <math.h>

// Problem dims
#define BB_ 16
#define T_ 64
#define S_ 32
#define F_ 128
#define H_ 128
#define NH_ 4

// ---------------- scratch (no allocations allowed) ----------------
__device__ float g_att4[BB_*NH_*H_*S_];  // attention outputs (pre head-mean)
__device__ float g_part[3*32*BB_*H_];    // gate split-K partials
__device__ float g_fc[BB_*2*H_];         // fc out (mu|logvar)
__device__ float g_h2[BB_*H_];           // decoder h2

// grid-barrier state (sense-reversing via generation counter)
__device__ unsigned int g_cnt = 0;
__device__ unsigned int g_gen = 0;

#define NB_ 128

__device__ __forceinline__ void grid_barrier(int nb){
  __syncthreads();
  if (threadIdx.x == 0) {
    __threadfence();
    unsigned int gen = *((volatile unsigned int*)&g_gen);
    unsigned int old = atomicAdd(&g_cnt, 1u);
    if (old == (unsigned int)nb - 1u) {
      *((volatile unsigned int*)&g_cnt) = 0u;
      __threadfence();
      atomicAdd(&g_gen, 1u);
    } else {
      while (*((volatile unsigned int*)&g_gen) == gen) { }
    }
    __threadfence();
  }
  __syncthreads();
}

__device__ __forceinline__ unsigned int rotl32_(unsigned int v, int d){ return (v << d) | (v >> (32 - d)); }

// Neumaier compensated accumulate (kept in the cheap, KL-sensitive tail).
__device__ __forceinline__ void kadd_(float& s, float& c, float p){
  float t = s + p;
  c += (fabsf(s) >= fabsf(p)) ? ((s - t) + p) : ((p - t) + s);
  s = t;
}

// Exact JAX threefry2x32 (20 rounds), key = (k0, k1)
__device__ __forceinline__ void threefry2x32_(unsigned int k0, unsigned int k1,
    unsigned int c0, unsigned int c1, unsigned int& o0, unsigned int& o1)
{
  unsigned int ks2 = k0 ^ k1 ^ 0x1BD11BDAu;
  unsigned int x0 = c0 + k0, x1 = c1 + k1;
  const int ra[4] = {13,15,26,6};
  const int rb[4] = {17,29,16,24};
  #pragma unroll
  for (int i=0;i<4;i++){ x0 += x1; x1 = rotl32_(x1, ra[i]); x1 ^= x0; }
  x0 += k1; x1 += ks2 + 1u;
  #pragma unroll
  for (int i=0;i<4;i++){ x0 += x1; x1 = rotl32_(x1, rb[i]); x1 ^= x0; }
  x0 += ks2; x1 += k0 + 2u;
  #pragma unroll
  for (int i=0;i<4;i++){ x0 += x1; x1 = rotl32_(x1, ra[i]); x1 ^= x0; }
  x0 += k0; x1 += k1 + 3u;
  #pragma unroll
  for (int i=0;i<4;i++){ x0 += x1; x1 = rotl32_(x1, rb[i]); x1 ^= x0; }
  x0 += k1; x1 += ks2 + 4u;
  #pragma unroll
  for (int i=0;i<4;i++){ x0 += x1; x1 = rotl32_(x1, ra[i]); x1 ^= x0; }
  x0 += ks2; x1 += k0 + 5u;
  o0 = x0; o1 = x1;
}

// ---------------- fused encoder pass, 128 co-resident blocks x 512 threads ----------
// Stage AB: one (b, n, half) unit per block — hid in registers, k/v/q + attention in smem.
// Stage C: gates GEMM (2 sub-blocks of 256 per block). Stage D: reduce+LSTM+fc.
// Stage E: reparam + KL (+ decode MLP).
__global__ void __launch_bounds__(512) enc_kernel(
    const float* __restrict__ xsrc,
    const float* __restrict__ w_enc, const float* __restrict__ b_enc,
    const float* __restrict__ wq, const float* __restrict__ bq,
    const float* __restrict__ wk, const float* __restrict__ bk,
    const float* __restrict__ wv, const float* __restrict__ bv,
    const float* __restrict__ Wii, const float* __restrict__ Wig, const float* __restrict__ Wio,
    const float* __restrict__ w_fc, const float* __restrict__ b_fc,
    unsigned int keylo, float* __restrict__ z_out, float* __restrict__ kl_out,
    int do_dec,
    const float* __restrict__ w_d1, const float* __restrict__ b_d1,
    const float* __restrict__ w_d2, const float* __restrict__ b_d2)
{
  // pool layout (floats):
  // [0..4127]      xs[32][129]  -> later kT[32][129] (kT[s*129+g])
  // [4128..8223]   v[128][32]
  // [8224..10271]  q[64][32]
  // [10272..11295] wk_sm[32][32]
  __shared__ __align__(16) float pool[11296];
  int blk = blockIdx.x, tid = threadIdx.x;
  int warp = tid >> 5, lane = tid & 31;

  // ================= stage AB: hid + qkv + attention, one unit per block ==========
  {
    float* xs   = pool;            // then kT
    float* vsm  = pool + 4128;
    float* qsm  = pool + 8224;
    float* wksm = pool + 10272;
    int b = blk >> 3, n = (blk >> 1) & 3, half = blk & 1;
    const float* xb = xsrc + (size_t)b*(T_*S_*F_) + (size_t)(T_-1)*(S_*F_);
    for (int i = tid; i < 4096; i += 512)
      xs[(i>>7)*129 + (i&127)] = xb[i];
    for (int i = tid; i < 1024; i += 512)
      wksm[i] = wk[(i>>5)*(S_*NH_) + n*S_ + (i&31)];
    __syncthreads();

    // hid: warp owns rows h = warp*8 .. warp*8+7; lane = s. float4 w_enc loads.
    float hid_r[8];
    #pragma unroll
    for (int g4 = 0; g4 < 2; g4++) {
      int h0 = warp*8 + g4*4;
      float p[4][4];
      #pragma unroll
      for (int r = 0; r < 4; r++)
        #pragma unroll
        for (int fb = 0; fb < 4; fb++) p[r][fb] = 0.f;
      #pragma unroll
      for (int fb = 0; fb < 4; fb++)
        #pragma unroll 8
        for (int f0 = 0; f0 < 32; f0++) {
          int f = fb*32 + f0;
          float xv = xs[lane*129 + f];
          float4 w4 = *(const float4*)(w_enc + (size_t)f*H_ + h0);
          p[0][fb] = fmaf(xv, w4.x, p[0][fb]);
          p[1][fb] = fmaf(xv, w4.y, p[1][fb]);
          p[2][fb] = fmaf(xv, w4.z, p[2][fb]);
          p[3][fb] = fmaf(xv, w4.w, p[3][fb]);
        }
      #pragma unroll
      for (int r = 0; r < 4; r++)
        hid_r[g4*4+r] = ((p[r][0]+p[r][1])+(p[r][2]+p[r][3])) + b_enc[h0+r];
    }
    __syncthreads();   // xs dead; kT will overwrite

    // qkv: k,v full (all warps); q only for rows in this block's half.
    const float scale = 0.08838834764831845f; // 1/sqrt(H)
    bool doq = (warp >= half*8) && (warp < half*8 + 8);
    #pragma unroll
    for (int rr = 0; rr < 8; rr++) {
      int h = warp*8 + rr;
      float pk[4] = {0.f,0.f,0.f,0.f};
      float pv[4] = {0.f,0.f,0.f,0.f};
      float pq[4] = {0.f,0.f,0.f,0.f};
      #pragma unroll
      for (int sb = 0; sb < 4; sb++)
        #pragma unroll
        for (int s0 = 0; s0 < 8; s0++) {
          int sp = sb*8 + s0;
          float hv = __shfl_sync(0xffffffffu, hid_r[rr], sp);
          pk[sb] = fmaf(hv, wksm[sp*32 + lane], pk[sb]);
          pv[sb] = fmaf(hv, wv[sp*(S_*NH_) + n*S_ + lane], pv[sb]);
          if (doq)
            pq[sb] = fmaf(hv, wq[sp*(S_*NH_) + n*S_ + lane], pq[sb]);
        }
      xs[lane*129 + h] = ((pk[0]+pk[1])+(pk[2]+pk[3])) + bk[n*S_+lane];   // kT[s][g]
      vsm[h*32 + lane] = ((pv[0]+pv[1])+(pv[2]+pv[3])) + bv[n*S_+lane];
      if (doq)
        qsm[(h - half*64)*32 + lane] =
          (((pq[0]+pq[1])+(pq[2]+pq[3])) + bq[n*S_+lane]) * scale;
    }
    __syncthreads();

    // attention: warp handles local rows warp*4 + r (64 rows per block).
    size_t base = ((size_t)(b*NH_ + n))*(H_*S_);
    #pragma unroll
    for (int r = 0; r < 4; r++) {
      int lrow = warp*4 + r;
      float lg[4];
      #pragma unroll
      for (int j = 0; j < 4; j++) {
        int g = lane + 32*j;
        float pp[4] = {0.f,0.f,0.f,0.f};
        #pragma unroll
        for (int sb = 0; sb < 4; sb++)
          #pragma unroll
          for (int s0 = 0; s0 < 8; s0++) {
            int s = sb*8 + s0;
            pp[sb] = fmaf(qsm[lrow*32+s], xs[s*129+g], pp[sb]);
          }
        lg[j] = (pp[0]+pp[1]) + (pp[2]+pp[3]);
      }
      float m = fmaxf(fmaxf(lg[0],lg[1]), fmaxf(lg[2],lg[3]));
      #pragma unroll
      for (int o = 16; o; o >>= 1) m = fmaxf(m, __shfl_xor_sync(0xffffffffu, m, o));
      float ssum = 0.f;
      #pragma unroll
      for (int j = 0; j < 4; j++){ lg[j] = expf(lg[j]-m); ssum += lg[j]; }
      #pragma unroll
      for (int o = 16; o; o >>= 1) ssum += __shfl_xor_sync(0xffffffffu, ssum, o);
      float inv = 1.f/ssum;
      #pragma unroll
      for (int j = 0; j < 4; j++) lg[j] *= inv;   // normalized probs in regs
      float pp2[8] = {0.f,0.f,0.f,0.f,0.f,0.f,0.f,0.f};
      #pragma unroll
      for (int gb = 0; gb < 8; gb++)
        #pragma unroll
        for (int g0 = 0; g0 < 16; g0++) {
          int g = gb*16 + g0;
          float pwv = __shfl_sync(0xffffffffu, lg[g>>5], g & 31);
          pp2[gb] = fmaf(pwv, vsm[g*32 + lane], pp2[gb]);
        }
      float acc = ((pp2[0]+pp2[1])+(pp2[2]+pp2[3])) + ((pp2[4]+pp2[5])+(pp2[6]+pp2[7]));
      g_att4[base + (size_t)(half*64 + lrow)*S_ + lane] = acc;
    }
  }
  grid_barrier(NB_);

  // ================= stage C: gate GEMM (fused head-mean+ReLU) ====================
  // 192 units over 128 blocks as 2 sub-blocks of 256 threads (one unit each).
  {
    int sid = tid >> 8, tid2 = tid & 255;
    int su = blk*2 + sid;
    if (su < 192) {        // uniform per block (both subs active iff blk < 96)
      float* as = pool + sid*1024;
      int gate = su / 64;
      int rem  = su - gate*64;
      int chunk = rem >> 1, bh = rem & 1;
      const float* Wm = (gate == 0) ? Wii : (gate == 1) ? Wig : Wio;
      int j0 = chunk*128;
      for (int i = tid2; i < 8*128; i += 256) {
        int bb = i >> 7, j = i & 127;
        int bg = bh*8 + bb;
        size_t bbase = (size_t)bg*4*(H_*S_);
        int hs = j0 + j;
        float v = (g_att4[bbase + hs] + g_att4[bbase + 4096 + hs])
                + (g_att4[bbase + 8192 + hs] + g_att4[bbase + 12288 + hs]);
        v *= 0.25f;
        as[i] = v > 0.f ? v : 0.f;
      }
      __syncthreads();
      int m = tid2 & 127, hlf = tid2 >> 7;
      float acc[4][4];
      #pragma unroll
      for (int bb = 0; bb < 4; bb++)
        #pragma unroll
        for (int jb = 0; jb < 4; jb++) acc[bb][jb] = 0.f;
      #pragma unroll
      for (int jb = 0; jb < 4; jb++)
        #pragma unroll 8
        for (int j0i = 0; j0i < 32; j0i++) {
          int j = jb*32 + j0i;
          float w = Wm[(size_t)(j0+j)*H_ + m];
          #pragma unroll
          for (int bb = 0; bb < 4; bb++)
            acc[bb][jb] = fmaf(as[(hlf*4+bb)*128 + j], w, acc[bb][jb]);
        }
      size_t cbase = ((size_t)(gate*32 + chunk))*(BB_*H_);
      #pragma unroll
      for (int bb = 0; bb < 4; bb++)
        g_part[cbase + (bh*8 + hlf*4 + bb)*H_ + m] =
          (acc[bb][0]+acc[bb][1]) + (acc[bb][2]+acc[bb][3]);
    }
  }
  grid_barrier(NB_);

  // ================= stage D: reduce + LSTM + fc (one batch row per block) ========
  if (blk < 16) {
    float* s_g = pool;         // 384
    float* s_h = pool + 384;   // 128
    int b = blk;
    for (int idx = tid; idx < 384; idx += 512) {
      int gate = idx >> 7, m = idx & 127;
      int r = b*128 + m;
      float s = 0.f, c = 0.f;
      #pragma unroll
      for (int ch = 0; ch < 32; ch++)
        kadd_(s, c, g_part[(size_t)(gate*32 + ch)*(BB_*H_) + r]);
      s_g[gate*128 + m] = s + c;
    }
    __syncthreads();
    if (tid < 128) {
      double iv = 1.0/(1.0 + exp(-(double)s_g[tid]));
      double gv = tanh((double)s_g[128 + tid]);
      double ov = 1.0/(1.0 + exp(-(double)s_g[256 + tid]));
      s_h[tid] = (float)(ov * tanh(iv * gv));
    }
    __syncthreads();
    if (tid < 256) {
      int c = tid;
      float s = 0.f, cc = 0.f;
      #pragma unroll 8
      for (int mm = 0; mm < 128; mm++)
        kadd_(s, cc, s_h[mm] * w_fc[mm*256 + c]);
      g_fc[b*256 + c] = (s + cc) + b_fc[c];
    }
  }
  grid_barrier(NB_);

  // ================= stage E: reparam + KL (+ decode MLP), block 0 only ===========
  if (blk == 0) {
    float* h1    = pool;                        // 2048 (dec)
    float* s_z   = pool + 4096;                 // 2048
    double* redd = (double*)(pool + 6144);      // 512 doubles
    double kacc = 0.0;
    for (int idx = tid; idx < 2048; idx += 512) {
      int bb = idx >> 7, k = idx & 127;
      float mu = g_fc[bb*256 + k];
      float lv = g_fc[bb*256 + 128 + k];
      unsigned int o0, o1;
      threefry2x32_(0u, keylo, 0u, (unsigned int)idx, o0, o1);
      unsigned int bits = o0 ^ o1;
      float f = __uint_as_float((bits >> 9) | 0x3f800000u) - 1.0f;   // [0,1)
      const float lo = -0.99999994f;                                 // nextafter(-1,0)
      float u = fmaxf(lo, fmaf(f, 2.0f, lo));
      float eps = 1.4142135623730951f * erfinvf(u);
      float zv = fmaf(eps, expf(0.5f*lv), mu);
      z_out[idx] = zv;
      s_z[idx] = zv;
      double dmu = (double)mu, dlv = (double)lv;
      kacc += 1.0 + dlv - dmu*dmu - exp(dlv);
    }
    redd[tid] = kacc;
    __syncthreads();
    for (int o = 256; o; o >>= 1) {
      if (tid < o) redd[tid] += redd[tid + o];
      __syncthreads();
    }
    if (tid == 0) kl_out[0] = (float)(-0.5 * redd[0] * (1.0/2048.0));
    if (do_dec) {
      __syncthreads();
      for (int i = tid; i < 2048; i += 512) {
        int bb = i >> 7, c = i & 127;
        float p[4] = {0.f,0.f,0.f,0.f};
        #pragma unroll
        for (int jb = 0; jb < 4; jb++)
          #pragma unroll 8
          for (int j0 = 0; j0 < 32; j0++) {
            int j = jb*32 + j0;
            p[jb] = fmaf(s_z[bb*128+j], w_d1[j*128+c], p[jb]);
          }
        float acc = ((p[0]+p[1]) + (p[2]+p[3])) + b_d1[c];
        h1[i] = fmaxf(acc, 0.f);
      }
      __syncthreads();
      for (int i = tid; i < 2048; i += 512) {
        int bb = i >> 7, c = i & 127;
        float p[4] = {0.f,0.f,0.f,0.f};
        #pragma unroll
        for (int jb = 0; jb < 4; jb++)
          #pragma unroll 8
          for (int j0 = 0; j0 < 32; j0++) {
            int j = jb*32 + j0;
            p[jb] = fmaf(h1[bb*128+j], w_d2[j*128+c], p[jb]);
          }
        float acc = ((p[0]+p[1]) + (p[2]+p[3])) + b_d2[c];
        g_h2[i] = fmaxf(acc, 0.f);
      }
    }
  }
}

// ---------------- big decode GEMM h2[16,128] @ w_d3[128,262144] + b_d3 ----------------
__device__ __forceinline__ unsigned long long pk2_(float a, float b){
  return (unsigned long long)__float_as_uint(a) | ((unsigned long long)__float_as_uint(b) << 32);
}

__global__ void __launch_bounds__(256) big_kernel(
    const float* __restrict__ w_d3, const float* __restrict__ b_d3, float* __restrict__ out)
{
  __shared__ unsigned long long hp[8*128];   // (b-pair, j) packed h2 values
  int tid = threadIdx.x;
  for (int i = tid; i < 1024; i += 256) {
    int p = i >> 7, j = i & 127;
    hp[i] = pk2_(g_h2[(2*p)*128 + j], g_h2[(2*p+1)*128 + j]);
  }
  __syncthreads();
  size_t m2 = (size_t)blockIdx.x*256 + tid;    // float2 column index, < 131072
  const float2* w2 = (const float2*)w_d3;
  float2 bv2 = ((const float2*)b_d3)[m2];
  unsigned long long accx[8], accy[8];
  unsigned long long bx = pk2_(bv2.x, bv2.x), by = pk2_(bv2.y, bv2.y);
  #pragma unroll
  for (int p = 0; p < 8; p++){ accx[p] = bx; accy[p] = by; }
  #pragma unroll 4
  for (int j = 0; j < 128; j++) {
    float2 w = __ldg(&w2[(size_t)j*131072 + m2]);
    unsigned long long wx = pk2_(w.x, w.x), wy = pk2_(w.y, w.y);
    #pragma unroll
    for (int p = 0; p < 8; p++) {
      unsigned long long hpair = hp[p*128 + j];
      asm("fma.rn.f32x2 %0, %1, %2, %3;" : "=l"(accx[p]) : "l"(hpair), "l"(wx), "l"(accx[p]));
      asm("fma.rn.f32x2 %0, %1, %2, %3;" : "=l"(accy[p]) : "l"(hpair), "l"(wy), "l"(accy[p]));
    }
  }
  float2* o2 = (float2*)out;
  #pragma unroll
  for (int p = 0; p < 8; p++) {
    float2 v0, v1;
    v0.x = __uint_as_float((unsigned int)accx[p]);
    v0.y = __uint_as_float((unsigned int)accy[p]);
    v1.x = __uint_as_float((unsigned int)(accx[p] >> 32));
    v1.y = __uint_as_float((unsigned int)(accy[p] >> 32));
    o2[(size_t)(2*p)*131072 + m2]   = v0;
    o2[(size_t)(2*p+1)*131072 + m2] = v1;
  }
}

// ---------------- launcher (3 launches total) ----------------
extern "C" void kernel_launch(void* const* d_in, const int* in_sizes, int n_in,
                              void* d_out, int out_size)
{
  (void)in_sizes; (void)n_in; (void)out_size;
  const float* x     = (const float*)d_in[0];
  const float* w_enc = (const float*)d_in[1];
  const float* b_enc = (const float*)d_in[2];
  const float* wq    = (const float*)d_in[3];
  const float* bq    = (const float*)d_in[4];
  const float* wk    = (const float*)d_in[5];
  const float* bk    = (const float*)d_in[6];
  const float* wv    = (const float*)d_in[7];
  const float* bv    = (const float*)d_in[8];
  const float* W_ii  = (const float*)d_in[9];
  const float* W_ig  = (const float*)d_in[13];
  const float* W_io  = (const float*)d_in[15];
  const float* w_fc  = (const float*)d_in[17];
  const float* b_fc  = (const float*)d_in[18];
  const float* w_d1  = (const float*)d_in[19];
  const float* b_d1  = (const float*)d_in[20];
  const float* w_d2  = (const float*)d_in[21];
  const float* b_d2  = (const float*)d_in[22];
  const float* w_d3  = (const float*)d_in[23];
  const float* b_d3  = (const float*)d_in[24];

  float* outp = (float*)d_out;
  float* xhat = outp;                  // [16,64,32,128] = 4194304
  float* z1   = outp + 4194304;        // [16,128]
  float* z2   = z1 + 2048;             // [16,128]
  float* kl1  = z2 + 2048;             // scalar
  float* kl2  = kl1 + 1;               // scalar

  // -------- pass 1: encode(x, key=1) + decode MLP --------
  enc_kernel<<<NB_, 512>>>(x, w_enc, b_enc, wq, bq, wk, bk, wv, bv,
                           W_ii, W_ig, W_io, w_fc, b_fc,
                           1u, z1, kl1, 1, w_d1, b_d1, w_d2, b_d2);
  // -------- big decode GEMM --------
  big_kernel<<<512, 256>>>(w_d3, b_d3, xhat);
  // -------- pass 2: encode(x_hat1, key=2) --------
  enc_kernel<<<NB_, 512>>>(xhat, w_enc, b_enc, wq, bq, wk, bk, wv, bv,
                           W_ii, W_ig, W_io, w_fc, b_fc,
                           2u, z2, kl2, 0, w_d1, b_d1, w_d2, b_d2);
}

// round 13
// speedup vs baseline: 2.0952x; 1.1050x over previous
#include <cuda_runtime.h>
#include <math.h>

// Problem dims
#define BB_ 16
#define T_ 64
#define S_ 32
#define F_ 128
#define H_ 128
#define NH_ 4

// ---------------- scratch (no allocations allowed) ----------------
__device__ float g_att4[BB_*NH_*H_*S_];  // attention outputs (pre head-mean)
__device__ float g_part[3*32*BB_*H_];    // gate split-K partials
__device__ float g_fc[BB_*2*H_];         // fc out (mu|logvar)
__device__ float g_h2[BB_*H_];           // decoder h2

// grid-barrier state (sense-reversing via generation counter)
__device__ unsigned int g_cnt = 0;
__device__ unsigned int g_gen = 0;

#define NB_ 128

__device__ __forceinline__ void grid_barrier(int nb){
  __syncthreads();
  if (threadIdx.x == 0) {
    __threadfence();
    unsigned int gen = *((volatile unsigned int*)&g_gen);
    unsigned int old = atomicAdd(&g_cnt, 1u);
    if (old == (unsigned int)nb - 1u) {
      *((volatile unsigned int*)&g_cnt) = 0u;
      __threadfence();
      atomicAdd(&g_gen, 1u);
    } else {
      while (*((volatile unsigned int*)&g_gen) == gen) { }
    }
    __threadfence();
  }
  __syncthreads();
}

__device__ __forceinline__ unsigned int rotl32_(unsigned int v, int d){ return (v << d) | (v >> (32 - d)); }

// Neumaier compensated accumulate (kept in the cheap, KL-sensitive tail).
__device__ __forceinline__ void kadd_(float& s, float& c, float p){
  float t = s + p;
  c += (fabsf(s) >= fabsf(p)) ? ((s - t) + p) : ((p - t) + s);
  s = t;
}

// Exact JAX threefry2x32 (20 rounds), key = (k0, k1)
__device__ __forceinline__ void threefry2x32_(unsigned int k0, unsigned int k1,
    unsigned int c0, unsigned int c1, unsigned int& o0, unsigned int& o1)
{
  unsigned int ks2 = k0 ^ k1 ^ 0x1BD11BDAu;
  unsigned int x0 = c0 + k0, x1 = c1 + k1;
  const int ra[4] = {13,15,26,6};
  const int rb[4] = {17,29,16,24};
  #pragma unroll
  for (int i=0;i<4;i++){ x0 += x1; x1 = rotl32_(x1, ra[i]); x1 ^= x0; }
  x0 += k1; x1 += ks2 + 1u;
  #pragma unroll
  for (int i=0;i<4;i++){ x0 += x1; x1 = rotl32_(x1, rb[i]); x1 ^= x0; }
  x0 += ks2; x1 += k0 + 2u;
  #pragma unroll
  for (int i=0;i<4;i++){ x0 += x1; x1 = rotl32_(x1, ra[i]); x1 ^= x0; }
  x0 += k0; x1 += k1 + 3u;
  #pragma unroll
  for (int i=0;i<4;i++){ x0 += x1; x1 = rotl32_(x1, rb[i]); x1 ^= x0; }
  x0 += k1; x1 += ks2 + 4u;
  #pragma unroll
  for (int i=0;i<4;i++){ x0 += x1; x1 = rotl32_(x1, ra[i]); x1 ^= x0; }
  x0 += ks2; x1 += k0 + 5u;
  o0 = x0; o1 = x1;
}

// ---------------- fused encoder pass, 128 co-resident blocks x 512 threads ----------
__global__ void __launch_bounds__(512) enc_kernel(
    const float* __restrict__ xsrc,
    const float* __restrict__ w_enc, const float* __restrict__ b_enc,
    const float* __restrict__ wq, const float* __restrict__ bq,
    const float* __restrict__ wk, const float* __restrict__ bk,
    const float* __restrict__ wv, const float* __restrict__ bv,
    const float* __restrict__ Wii, const float* __restrict__ Wig, const float* __restrict__ Wio,
    const float* __restrict__ w_fc, const float* __restrict__ b_fc,
    unsigned int keylo, float* __restrict__ z_out, float* __restrict__ kl_out,
    int do_dec,
    const float* __restrict__ w_d1, const float* __restrict__ b_d1,
    const float* __restrict__ w_d2, const float* __restrict__ b_d2)
{
  // pool layout (floats):
  // [0..4127]      xs[32][129]  -> later kT[32][129] (kT[s*129+g])
  // [4128..8223]   v[128][32]
  // [8224..10271]  q[64][32]
  // [10272..11295] wk_sm[32][32]
  __shared__ __align__(16) float pool[11296];
  int blk = blockIdx.x, tid = threadIdx.x;
  int warp = tid >> 5, lane = tid & 31;

  // ================= stage AB: hid + qkv + attention, one unit per block ==========
  {
    float* xs   = pool;            // then kT
    float* vsm  = pool + 4128;
    float* qsm  = pool + 8224;
    float* wksm = pool + 10272;
    int b = blk >> 3, n = (blk >> 1) & 3, half = blk & 1;
    const float* xb = xsrc + (size_t)b*(T_*S_*F_) + (size_t)(T_-1)*(S_*F_);
    for (int i = tid; i < 4096; i += 512)
      xs[(i>>7)*129 + (i&127)] = xb[i];
    for (int i = tid; i < 1024; i += 512)
      wksm[i] = wk[(i>>5)*(S_*NH_) + n*S_ + (i&31)];
    __syncthreads();

    // hid: warp owns rows h = warp*8 .. warp*8+7; lane = s. float4 w_enc loads.
    float hid_r[8];
    #pragma unroll
    for (int g4 = 0; g4 < 2; g4++) {
      int h0 = warp*8 + g4*4;
      float p[4][4];
      #pragma unroll
      for (int r = 0; r < 4; r++)
        #pragma unroll
        for (int fb = 0; fb < 4; fb++) p[r][fb] = 0.f;
      #pragma unroll
      for (int fb = 0; fb < 4; fb++)
        #pragma unroll 8
        for (int f0 = 0; f0 < 32; f0++) {
          int f = fb*32 + f0;
          float xv = xs[lane*129 + f];
          float4 w4 = *(const float4*)(w_enc + (size_t)f*H_ + h0);
          p[0][fb] = fmaf(xv, w4.x, p[0][fb]);
          p[1][fb] = fmaf(xv, w4.y, p[1][fb]);
          p[2][fb] = fmaf(xv, w4.z, p[2][fb]);
          p[3][fb] = fmaf(xv, w4.w, p[3][fb]);
        }
      #pragma unroll
      for (int r = 0; r < 4; r++)
        hid_r[g4*4+r] = ((p[r][0]+p[r][1])+(p[r][2]+p[r][3])) + b_enc[h0+r];
    }
    __syncthreads();   // xs dead; kT will overwrite

    // qkv register-blocked: sp outer (weights loaded once), rr inner.
    const float scale = 0.08838834764831845f; // 1/sqrt(H)
    bool doq = (warp >= half*8) && (warp < half*8 + 8);
    float accK[8], accV[8], accQ[8];
    #pragma unroll
    for (int rr = 0; rr < 8; rr++){ accK[rr]=0.f; accV[rr]=0.f; accQ[rr]=0.f; }
    #pragma unroll 4
    for (int sp = 0; sp < 32; sp++) {
      float wkv = wksm[sp*32 + lane];
      float wqv = __ldg(wq + sp*(S_*NH_) + n*S_ + lane);
      float wvv = __ldg(wv + sp*(S_*NH_) + n*S_ + lane);
      #pragma unroll
      for (int rr = 0; rr < 8; rr++) {
        float hv = __shfl_sync(0xffffffffu, hid_r[rr], sp);
        accK[rr] = fmaf(hv, wkv, accK[rr]);
        accV[rr] = fmaf(hv, wvv, accV[rr]);
        if (doq) accQ[rr] = fmaf(hv, wqv, accQ[rr]);
      }
    }
    #pragma unroll
    for (int rr = 0; rr < 8; rr++) {
      int h = warp*8 + rr;
      xs[lane*129 + h] = accK[rr] + bk[n*S_+lane];       // kT[s][g]
      vsm[h*32 + lane] = accV[rr] + bv[n*S_+lane];
      if (doq)
        qsm[(h - half*64)*32 + lane] = (accQ[rr] + bq[n*S_+lane]) * scale;
    }
    __syncthreads();

    // attention: warp owns 4 local rows; q rows in registers (lane = s).
    size_t base = ((size_t)(b*NH_ + n))*(H_*S_);
    float q_reg[4];
    #pragma unroll
    for (int r = 0; r < 4; r++) q_reg[r] = qsm[(warp*4 + r)*32 + lane];

    // QK: logit[r][g = lane+32j]
    float lg[4][4];
    #pragma unroll
    for (int r = 0; r < 4; r++)
      #pragma unroll
      for (int j = 0; j < 4; j++) lg[r][j] = 0.f;
    #pragma unroll 8
    for (int s = 0; s < 32; s++) {
      float kv0 = xs[s*129 + lane];
      float kv1 = xs[s*129 + lane + 32];
      float kv2 = xs[s*129 + lane + 64];
      float kv3 = xs[s*129 + lane + 96];
      #pragma unroll
      for (int r = 0; r < 4; r++) {
        float qv = __shfl_sync(0xffffffffu, q_reg[r], s);
        lg[r][0] = fmaf(qv, kv0, lg[r][0]);
        lg[r][1] = fmaf(qv, kv1, lg[r][1]);
        lg[r][2] = fmaf(qv, kv2, lg[r][2]);
        lg[r][3] = fmaf(qv, kv3, lg[r][3]);
      }
    }
    // softmax per row (normalized probs stay in lg)
    #pragma unroll
    for (int r = 0; r < 4; r++) {
      float m = fmaxf(fmaxf(lg[r][0],lg[r][1]), fmaxf(lg[r][2],lg[r][3]));
      #pragma unroll
      for (int o = 16; o; o >>= 1) m = fmaxf(m, __shfl_xor_sync(0xffffffffu, m, o));
      float ssum = 0.f;
      #pragma unroll
      for (int j = 0; j < 4; j++){ lg[r][j] = expf(lg[r][j]-m); ssum += lg[r][j]; }
      #pragma unroll
      for (int o = 16; o; o >>= 1) ssum += __shfl_xor_sync(0xffffffffu, ssum, o);
      float inv = 1.f/ssum;
      #pragma unroll
      for (int j = 0; j < 4; j++) lg[r][j] *= inv;
    }
    // PV tiled: share each v load across the 4 rows; 4 g-block partials per row.
    float accP[4][4];
    #pragma unroll
    for (int r = 0; r < 4; r++)
      #pragma unroll
      for (int gb = 0; gb < 4; gb++) accP[r][gb] = 0.f;
    #pragma unroll
    for (int gb = 0; gb < 4; gb++) {
      #pragma unroll 8
      for (int g0 = 0; g0 < 32; g0++) {
        int g = gb*32 + g0;
        float vv = vsm[g*32 + lane];
        #pragma unroll
        for (int r = 0; r < 4; r++) {
          float pwv = __shfl_sync(0xffffffffu, lg[r][gb], g0);
          accP[r][gb] = fmaf(pwv, vv, accP[r][gb]);
        }
      }
    }
    #pragma unroll
    for (int r = 0; r < 4; r++) {
      float acc = (accP[r][0]+accP[r][1]) + (accP[r][2]+accP[r][3]);
      g_att4[base + (size_t)(half*64 + warp*4 + r)*S_ + lane] = acc;
    }
  }
  grid_barrier(NB_);

  // ================= stage C: gate GEMM (fused head-mean+ReLU) ====================
  // 192 units over 128 blocks as 2 sub-blocks of 256 threads (one unit each).
  {
    int sid = tid >> 8, tid2 = tid & 255;
    int su = blk*2 + sid;
    if (su < 192) {
      float* as = pool + sid*1024;
      int gate = su / 64;
      int rem  = su - gate*64;
      int chunk = rem >> 1, bh = rem & 1;
      const float* Wm = (gate == 0) ? Wii : (gate == 1) ? Wig : Wio;
      int j0 = chunk*128;
      for (int i = tid2; i < 8*128; i += 256) {
        int bb = i >> 7, j = i & 127;
        int bg = bh*8 + bb;
        size_t bbase = (size_t)bg*4*(H_*S_);
        int hs = j0 + j;
        float v = (g_att4[bbase + hs] + g_att4[bbase + 4096 + hs])
                + (g_att4[bbase + 8192 + hs] + g_att4[bbase + 12288 + hs]);
        v *= 0.25f;
        as[i] = v > 0.f ? v : 0.f;
      }
      __syncthreads();
      int m = tid2 & 127, hlf = tid2 >> 7;
      float acc[4][4];
      #pragma unroll
      for (int bb = 0; bb < 4; bb++)
        #pragma unroll
        for (int jb = 0; jb < 4; jb++) acc[bb][jb] = 0.f;
      #pragma unroll
      for (int jb = 0; jb < 4; jb++)
        #pragma unroll 8
        for (int j0i = 0; j0i < 32; j0i++) {
          int j = jb*32 + j0i;
          float w = Wm[(size_t)(j0+j)*H_ + m];
          #pragma unroll
          for (int bb = 0; bb < 4; bb++)
            acc[bb][jb] = fmaf(as[(hlf*4+bb)*128 + j], w, acc[bb][jb]);
        }
      size_t cbase = ((size_t)(gate*32 + chunk))*(BB_*H_);
      #pragma unroll
      for (int bb = 0; bb < 4; bb++)
        g_part[cbase + (bh*8 + hlf*4 + bb)*H_ + m] =
          (acc[bb][0]+acc[bb][1]) + (acc[bb][2]+acc[bb][3]);
    }
  }
  grid_barrier(NB_);

  // ================= stage D: reduce + LSTM + fc (one batch row per block) ========
  if (blk < 16) {
    float* s_g = pool;         // 384
    float* s_h = pool + 384;   // 128
    int b = blk;
    for (int idx = tid; idx < 384; idx += 512) {
      int gate = idx >> 7, m = idx & 127;
      int r = b*128 + m;
      float s = 0.f, c = 0.f;
      #pragma unroll
      for (int ch = 0; ch < 32; ch++)
        kadd_(s, c, g_part[(size_t)(gate*32 + ch)*(BB_*H_) + r]);
      s_g[gate*128 + m] = s + c;
    }
    __syncthreads();
    if (tid < 128) {
      double iv = 1.0/(1.0 + exp(-(double)s_g[tid]));
      double gv = tanh((double)s_g[128 + tid]);
      double ov = 1.0/(1.0 + exp(-(double)s_g[256 + tid]));
      s_h[tid] = (float)(ov * tanh(iv * gv));
    }
    __syncthreads();
    if (tid < 256) {
      int c = tid;
      float s = 0.f, cc = 0.f;
      #pragma unroll 8
      for (int mm = 0; mm < 128; mm++)
        kadd_(s, cc, s_h[mm] * w_fc[mm*256 + c]);
      g_fc[b*256 + c] = (s + cc) + b_fc[c];
    }
  }
  grid_barrier(NB_);

  // ================= stage E: reparam + KL on block 0 =============================
  if (blk == 0) {
    float* s_z   = pool + 4096;                 // 2048 (unused later; kept for clarity)
    double* redd = (double*)(pool + 6144);      // 512 doubles
    double kacc = 0.0;
    for (int idx = tid; idx < 2048; idx += 512) {
      int bb = idx >> 7, k = idx & 127;
      float mu = g_fc[bb*256 + k];
      float lv = g_fc[bb*256 + 128 + k];
      unsigned int o0, o1;
      threefry2x32_(0u, keylo, 0u, (unsigned int)idx, o0, o1);
      unsigned int bits = o0 ^ o1;
      float f = __uint_as_float((bits >> 9) | 0x3f800000u) - 1.0f;   // [0,1)
      const float lo = -0.99999994f;                                 // nextafter(-1,0)
      float u = fmaxf(lo, fmaf(f, 2.0f, lo));
      float eps = 1.4142135623730951f * erfinvf(u);
      float zv = fmaf(eps, expf(0.5f*lv), mu);
      z_out[idx] = zv;
      s_z[idx] = zv;
      double dmu = (double)mu, dlv = (double)lv;
      kacc += 1.0 + dlv - dmu*dmu - exp(dlv);
    }
    redd[tid] = kacc;
    __syncthreads();
    for (int o = 256; o; o >>= 1) {
      if (tid < o) redd[tid] += redd[tid + o];
      __syncthreads();
    }
    if (tid == 0) kl_out[0] = (float)(-0.5 * redd[0] * (1.0/2048.0));
  }

  // ================= stage F: decode MLP on 16 blocks (pass 1 only) ===============
  if (do_dec) {
    grid_barrier(NB_);        // z_out visible to all blocks
    if (blk < 16) {
      float* zsm = pool;        // 128
      float* h1  = pool + 128;  // 128
      int bb = blk;
      if (tid < 128) zsm[tid] = z_out[bb*128 + tid];
      __syncthreads();
      if (tid < 128) {
        int c = tid;
        float p[4] = {0.f,0.f,0.f,0.f};
        #pragma unroll
        for (int jb = 0; jb < 4; jb++)
          #pragma unroll 8
          for (int j0 = 0; j0 < 32; j0++) {
            int j = jb*32 + j0;
            p[jb] = fmaf(zsm[j], w_d1[j*128+c], p[jb]);
          }
        h1[c] = fmaxf(((p[0]+p[1]) + (p[2]+p[3])) + b_d1[c], 0.f);
      }
      __syncthreads();
      if (tid < 128) {
        int c = tid;
        float p[4] = {0.f,0.f,0.f,0.f};
        #pragma unroll
        for (int jb = 0; jb < 4; jb++)
          #pragma unroll 8
          for (int j0 = 0; j0 < 32; j0++) {
            int j = jb*32 + j0;
            p[jb] = fmaf(h1[j], w_d2[j*128+c], p[jb]);
          }
        g_h2[bb*128 + c] = fmaxf(((p[0]+p[1]) + (p[2]+p[3])) + b_d2[c], 0.f);
      }
    }
  }
}

// ---------------- big decode GEMM h2[16,128] @ w_d3[128,262144] + b_d3 ----------------
__device__ __forceinline__ unsigned long long pk2_(float a, float b){
  return (unsigned long long)__float_as_uint(a) | ((unsigned long long)__float_as_uint(b) << 32);
}

__global__ void __launch_bounds__(256) big_kernel(
    const float* __restrict__ w_d3, const float* __restrict__ b_d3, float* __restrict__ out)
{
  __shared__ unsigned long long hp[8*128];   // (b-pair, j) packed h2 values
  int tid = threadIdx.x;
  for (int i = tid; i < 1024; i += 256) {
    int p = i >> 7, j = i & 127;
    hp[i] = pk2_(g_h2[(2*p)*128 + j], g_h2[(2*p+1)*128 + j]);
  }
  __syncthreads();
  size_t m2 = (size_t)blockIdx.x*256 + tid;    // float2 column index, < 131072
  const float2* w2 = (const float2*)w_d3;
  float2 bv2 = ((const float2*)b_d3)[m2];
  unsigned long long accx[8], accy[8];
  unsigned long long bx = pk2_(bv2.x, bv2.x), by = pk2_(bv2.y, bv2.y);
  #pragma unroll
  for (int p = 0; p < 8; p++){ accx[p] = bx; accy[p] = by; }
  #pragma unroll 4
  for (int j = 0; j < 128; j++) {
    float2 w = __ldg(&w2[(size_t)j*131072 + m2]);
    unsigned long long wx = pk2_(w.x, w.x), wy = pk2_(w.y, w.y);
    #pragma unroll
    for (int p = 0; p < 8; p++) {
      unsigned long long hpair = hp[p*128 + j];
      asm("fma.rn.f32x2 %0, %1, %2, %3;" : "=l"(accx[p]) : "l"(hpair), "l"(wx), "l"(accx[p]));
      asm("fma.rn.f32x2 %0, %1, %2, %3;" : "=l"(accy[p]) : "l"(hpair), "l"(wy), "l"(accy[p]));
    }
  }
  float2* o2 = (float2*)out;
  #pragma unroll
  for (int p = 0; p < 8; p++) {
    float2 v0, v1;
    v0.x = __uint_as_float((unsigned int)accx[p]);
    v0.y = __uint_as_float((unsigned int)accy[p]);
    v1.x = __uint_as_float((unsigned int)(accx[p] >> 32));
    v1.y = __uint_as_float((unsigned int)(accy[p] >> 32));
    o2[(size_t)(2*p)*131072 + m2]   = v0;
    o2[(size_t)(2*p+1)*131072 + m2] = v1;
  }
}

// ---------------- launcher (3 launches total) ----------------
extern "C" void kernel_launch(void* const* d_in, const int* in_sizes, int n_in,
                              void* d_out, int out_size)
{
  (void)in_sizes; (void)n_in; (void)out_size;
  const float* x     = (const float*)d_in[0];
  const float* w_enc = (const float*)d_in[1];
  const float* b_enc = (const float*)d_in[2];
  const float* wq    = (const float*)d_in[3];
  const float* bq    = (const float*)d_in[4];
  const float* wk    = (const float*)d_in[5];
  const float* bk    = (const float*)d_in[6];
  const float* wv    = (const float*)d_in[7];
  const float* bv    = (const float*)d_in[8];
  const float* W_ii  = (const float*)d_in[9];
  const float* W_ig  = (const float*)d_in[13];
  const float* W_io  = (const float*)d_in[15];
  const float* w_fc  = (const float*)d_in[17];
  const float* b_fc  = (const float*)d_in[18];
  const float* w_d1  = (const float*)d_in[19];
  const float* b_d1  = (const float*)d_in[20];
  const float* w_d2  = (const float*)d_in[21];
  const float* b_d2  = (const float*)d_in[22];
  const float* w_d3  = (const float*)d_in[23];
  const float* b_d3  = (const float*)d_in[24];

  float* outp = (float*)d_out;
  float* xhat = outp;                  // [16,64,32,128] = 4194304
  float* z1   = outp + 4194304;        // [16,128]
  float* z2   = z1 + 2048;             // [16,128]
  float* kl1  = z2 + 2048;             // scalar
  float* kl2  = kl1 + 1;               // scalar

  // -------- pass 1: encode(x, key=1) + decode MLP --------
  enc_kernel<<<NB_, 512>>>(x, w_enc, b_enc, wq, bq, wk, bk, wv, bv,
                           W_ii, W_ig, W_io, w_fc, b_fc,
                           1u, z1, kl1, 1, w_d1, b_d1, w_d2, b_d2);
  // -------- big decode GEMM --------
  big_kernel<<<512, 256>>>(w_d3, b_d3, xhat);
  // -------- pass 2: encode(x_hat1, key=2) --------
  enc_kernel<<<NB_, 512>>>(xhat, w_enc, b_enc, wq, bq, wk, bk, wv, bv,
                           W_ii, W_ig, W_io, w_fc, b_fc,
                           2u, z2, kl2, 0, w_d1, b_d1, w_d2, b_d2);
}

// round 14
// speedup vs baseline: 2.2087x; 1.0542x over previous
#include <cuda_runtime.h>
#include <math.h>

// Problem dims
#define BB_ 16
#define T_ 64
#define S_ 32
#define F_ 128
#define H_ 128
#define NH_ 4

// ---------------- scratch (no allocations allowed) ----------------
__device__ float g_hid[BB_*H_*S_];       // 65536  hid (t=T-1), computed once
__device__ float g_att4[BB_*NH_*H_*S_];  // attention outputs (pre head-mean)
__device__ float g_part[3*32*BB_*H_];    // gate split-K partials
__device__ float g_fc[BB_*2*H_];         // fc out (mu|logvar)
__device__ float g_h2[BB_*H_];           // decoder h2

// grid-barrier state (sense-reversing via generation counter)
__device__ unsigned int g_cnt = 0;
__device__ unsigned int g_gen = 0;

#define NB_ 128

__device__ __forceinline__ void grid_barrier(int nb){
  __syncthreads();
  if (threadIdx.x == 0) {
    __threadfence();
    unsigned int gen = *((volatile unsigned int*)&g_gen);
    unsigned int old = atomicAdd(&g_cnt, 1u);
    if (old == (unsigned int)nb - 1u) {
      *((volatile unsigned int*)&g_cnt) = 0u;
      __threadfence();
      atomicAdd(&g_gen, 1u);
    } else {
      while (*((volatile unsigned int*)&g_gen) == gen) { }
    }
    __threadfence();
  }
  __syncthreads();
}

__device__ __forceinline__ unsigned int rotl32_(unsigned int v, int d){ return (v << d) | (v >> (32 - d)); }

// Neumaier compensated accumulate (kept in the cheap, KL-sensitive tail).
__device__ __forceinline__ void kadd_(float& s, float& c, float p){
  float t = s + p;
  c += (fabsf(s) >= fabsf(p)) ? ((s - t) + p) : ((p - t) + s);
  s = t;
}

// Exact JAX threefry2x32 (20 rounds), key = (k0, k1)
__device__ __forceinline__ void threefry2x32_(unsigned int k0, unsigned int k1,
    unsigned int c0, unsigned int c1, unsigned int& o0, unsigned int& o1)
{
  unsigned int ks2 = k0 ^ k1 ^ 0x1BD11BDAu;
  unsigned int x0 = c0 + k0, x1 = c1 + k1;
  const int ra[4] = {13,15,26,6};
  const int rb[4] = {17,29,16,24};
  #pragma unroll
  for (int i=0;i<4;i++){ x0 += x1; x1 = rotl32_(x1, ra[i]); x1 ^= x0; }
  x0 += k1; x1 += ks2 + 1u;
  #pragma unroll
  for (int i=0;i<4;i++){ x0 += x1; x1 = rotl32_(x1, rb[i]); x1 ^= x0; }
  x0 += ks2; x1 += k0 + 2u;
  #pragma unroll
  for (int i=0;i<4;i++){ x0 += x1; x1 = rotl32_(x1, ra[i]); x1 ^= x0; }
  x0 += k0; x1 += k1 + 3u;
  #pragma unroll
  for (int i=0;i<4;i++){ x0 += x1; x1 = rotl32_(x1, rb[i]); x1 ^= x0; }
  x0 += k1; x1 += ks2 + 4u;
  #pragma unroll
  for (int i=0;i<4;i++){ x0 += x1; x1 = rotl32_(x1, ra[i]); x1 ^= x0; }
  x0 += ks2; x1 += k0 + 5u;
  o0 = x0; o1 = x1;
}

// ---------------- fused encoder pass, 128 co-resident blocks x 1024 threads ---------
__global__ void __launch_bounds__(1024) enc_kernel(
    const float* __restrict__ xsrc,
    const float* __restrict__ w_enc, const float* __restrict__ b_enc,
    const float* __restrict__ wq, const float* __restrict__ bq,
    const float* __restrict__ wk, const float* __restrict__ bk,
    const float* __restrict__ wv, const float* __restrict__ bv,
    const float* __restrict__ Wii, const float* __restrict__ Wig, const float* __restrict__ Wio,
    const float* __restrict__ w_fc, const float* __restrict__ b_fc,
    unsigned int keylo, float* __restrict__ z_out, float* __restrict__ kl_out,
    int do_dec,
    const float* __restrict__ w_d1, const float* __restrict__ b_d1,
    const float* __restrict__ w_d2, const float* __restrict__ b_d2)
{
  // pool (floats): [0..4127] xs / kT[32][129]; [4128..8223] v[128][32];
  // [8224..10271] q[64][32]; [10272..11295] wk_sm[32][32]
  __shared__ __align__(16) float pool[11296];
  int blk = blockIdx.x, tid = threadIdx.x;
  int warp = tid >> 5, lane = tid & 31;

  // ================= stage A0: hid once per (b, ht of 16 rows) =====================
  // Summation order identical to R13 hid (fb-blocks of 32, 4-way tree).
  {
    float* xs = pool;
    int b = blk >> 3, ht = blk & 7;
    const float* xb = xsrc + (size_t)b*(T_*S_*F_) + (size_t)(T_-1)*(S_*F_);
    for (int i = tid; i < 4096; i += 1024)
      xs[(i>>7)*129 + (i&127)] = xb[i];
    __syncthreads();
    if (tid < 512) {
      int s = tid & 31, hl = tid >> 5;          // hl 0..15
      int h = ht*16 + hl;
      float p[4] = {0.f,0.f,0.f,0.f};
      #pragma unroll
      for (int fb = 0; fb < 4; fb++)
        #pragma unroll 8
        for (int f0 = 0; f0 < 32; f0++) {
          int f = fb*32 + f0;
          p[fb] = fmaf(xs[s*129+f], w_enc[(size_t)f*H_ + h], p[fb]);
        }
      g_hid[b*(H_*S_) + h*S_ + s] = ((p[0]+p[1]) + (p[2]+p[3])) + b_enc[h];
    }
  }
  grid_barrier(NB_);

  // ================= stage AB: qkv + attention, one (b,n,half) unit per block ======
  {
    float* kT   = pool;            // kT[s*129+g]
    float* vsm  = pool + 4128;
    float* qsm  = pool + 8224;
    float* wksm = pool + 10272;
    int b = blk >> 3, n = (blk >> 1) & 3, half = blk & 1;
    if (tid < 1024) {
      // wk to smem (1 elem/thread)
      wksm[tid] = wk[(tid>>5)*(S_*NH_) + n*S_ + (tid&31)];
    }
    // hid rows for this warp (4 rows, lane = s) — coalesced LDG
    float hid_r[4];
    #pragma unroll
    for (int rr = 0; rr < 4; rr++)
      hid_r[rr] = g_hid[b*(H_*S_) + (warp*4+rr)*S_ + lane];
    __syncthreads();

    // qkv register-blocked: sp outer (weights loaded once), rr inner.
    const float scale = 0.08838834764831845f; // 1/sqrt(H)
    bool doq = (warp >= half*16) && (warp < half*16 + 16);
    float accK[4] = {0.f,0.f,0.f,0.f};
    float accV[4] = {0.f,0.f,0.f,0.f};
    float accQ[4] = {0.f,0.f,0.f,0.f};
    #pragma unroll 4
    for (int sp = 0; sp < 32; sp++) {
      float wkv = wksm[sp*32 + lane];
      float wqv = __ldg(wq + sp*(S_*NH_) + n*S_ + lane);
      float wvv = __ldg(wv + sp*(S_*NH_) + n*S_ + lane);
      #pragma unroll
      for (int rr = 0; rr < 4; rr++) {
        float hv = __shfl_sync(0xffffffffu, hid_r[rr], sp);
        accK[rr] = fmaf(hv, wkv, accK[rr]);
        accV[rr] = fmaf(hv, wvv, accV[rr]);
        if (doq) accQ[rr] = fmaf(hv, wqv, accQ[rr]);
      }
    }
    #pragma unroll
    for (int rr = 0; rr < 4; rr++) {
      int h = warp*4 + rr;
      kT[lane*129 + h] = accK[rr] + bk[n*S_+lane];
      vsm[h*32 + lane] = accV[rr] + bv[n*S_+lane];
      if (doq)
        qsm[(h - half*64)*32 + lane] = (accQ[rr] + bq[n*S_+lane]) * scale;
    }
    __syncthreads();

    // attention: 64 local rows over 32 warps = 2 rows/warp; q rows in regs (lane = s)
    size_t base = ((size_t)(b*NH_ + n))*(H_*S_);
    float q_reg[2];
    #pragma unroll
    for (int r = 0; r < 2; r++) q_reg[r] = qsm[(warp*2 + r)*32 + lane];

    float lg[2][4];
    #pragma unroll
    for (int r = 0; r < 2; r++)
      #pragma unroll
      for (int j = 0; j < 4; j++) lg[r][j] = 0.f;
    #pragma unroll 8
    for (int s = 0; s < 32; s++) {
      float kv0 = kT[s*129 + lane];
      float kv1 = kT[s*129 + lane + 32];
      float kv2 = kT[s*129 + lane + 64];
      float kv3 = kT[s*129 + lane + 96];
      #pragma unroll
      for (int r = 0; r < 2; r++) {
        float qv = __shfl_sync(0xffffffffu, q_reg[r], s);
        lg[r][0] = fmaf(qv, kv0, lg[r][0]);
        lg[r][1] = fmaf(qv, kv1, lg[r][1]);
        lg[r][2] = fmaf(qv, kv2, lg[r][2]);
        lg[r][3] = fmaf(qv, kv3, lg[r][3]);
      }
    }
    #pragma unroll
    for (int r = 0; r < 2; r++) {
      float m = fmaxf(fmaxf(lg[r][0],lg[r][1]), fmaxf(lg[r][2],lg[r][3]));
      #pragma unroll
      for (int o = 16; o; o >>= 1) m = fmaxf(m, __shfl_xor_sync(0xffffffffu, m, o));
      float ssum = 0.f;
      #pragma unroll
      for (int j = 0; j < 4; j++){ lg[r][j] = expf(lg[r][j]-m); ssum += lg[r][j]; }
      #pragma unroll
      for (int o = 16; o; o >>= 1) ssum += __shfl_xor_sync(0xffffffffu, ssum, o);
      float inv = 1.f/ssum;
      #pragma unroll
      for (int j = 0; j < 4; j++) lg[r][j] *= inv;
    }
    float accP[2][4];
    #pragma unroll
    for (int r = 0; r < 2; r++)
      #pragma unroll
      for (int gb = 0; gb < 4; gb++) accP[r][gb] = 0.f;
    #pragma unroll
    for (int gb = 0; gb < 4; gb++) {
      #pragma unroll 8
      for (int g0 = 0; g0 < 32; g0++) {
        int g = gb*32 + g0;
        float vv = vsm[g*32 + lane];
        #pragma unroll
        for (int r = 0; r < 2; r++) {
          float pwv = __shfl_sync(0xffffffffu, lg[r][gb], g0);
          accP[r][gb] = fmaf(pwv, vv, accP[r][gb]);
        }
      }
    }
    #pragma unroll
    for (int r = 0; r < 2; r++) {
      float acc = (accP[r][0]+accP[r][1]) + (accP[r][2]+accP[r][3]);
      g_att4[base + (size_t)(half*64 + warp*2 + r)*S_ + lane] = acc;
    }
  }
  grid_barrier(NB_);

  // ================= stage C: gate GEMM (fused head-mean+ReLU) ====================
  // 96 units = gate(3) x chunk(32); one unit per block (blocks >= 96 idle).
  // Per-output j-order identical to R13 (jb-blocks of 32, 4-way tree).
  if (blk < 96) {
    float* as = pool;   // 16*128
    int gate = blk / 32, chunk = blk & 31;
    const float* Wm = (gate == 0) ? Wii : (gate == 1) ? Wig : Wio;
    int j0 = chunk*128;
    for (int i = tid; i < 16*128; i += 1024) {
      int bb = i >> 7, j = i & 127;
      size_t bbase = (size_t)bb*4*(H_*S_);
      int hs = j0 + j;
      float v = (g_att4[bbase + hs] + g_att4[bbase + 4096 + hs])
              + (g_att4[bbase + 8192 + hs] + g_att4[bbase + 12288 + hs]);
      v *= 0.25f;
      as[i] = v > 0.f ? v : 0.f;
    }
    __syncthreads();
    int m = tid & 127, oct = tid >> 7;   // oct 0..7, 2 batch rows each
    float acc[2][4];
    #pragma unroll
    for (int bbi = 0; bbi < 2; bbi++)
      #pragma unroll
      for (int jb = 0; jb < 4; jb++) acc[bbi][jb] = 0.f;
    #pragma unroll
    for (int jb = 0; jb < 4; jb++)
      #pragma unroll 8
      for (int j0i = 0; j0i < 32; j0i++) {
        int j = jb*32 + j0i;
        float w = Wm[(size_t)(j0+j)*H_ + m];
        #pragma unroll
        for (int bbi = 0; bbi < 2; bbi++)
          acc[bbi][jb] = fmaf(as[(oct*2+bbi)*128 + j], w, acc[bbi][jb]);
      }
    size_t cbase = ((size_t)(gate*32 + chunk))*(BB_*H_);
    #pragma unroll
    for (int bbi = 0; bbi < 2; bbi++)
      g_part[cbase + (oct*2+bbi)*H_ + m] =
        (acc[bbi][0]+acc[bbi][1]) + (acc[bbi][2]+acc[bbi][3]);
  }
  grid_barrier(NB_);

  // ================= stage D: reduce + LSTM + fc (one batch row per block) ========
  if (blk < 16) {
    float* s_g = pool;         // 384
    float* s_h = pool + 384;   // 128
    int b = blk;
    if (tid < 384) {
      int gate = tid >> 7, m = tid & 127;
      int r = b*128 + m;
      float s = 0.f, c = 0.f;
      #pragma unroll
      for (int ch = 0; ch < 32; ch++)
        kadd_(s, c, g_part[(size_t)(gate*32 + ch)*(BB_*H_) + r]);
      s_g[gate*128 + m] = s + c;
    }
    __syncthreads();
    if (tid < 128) {
      double iv = 1.0/(1.0 + exp(-(double)s_g[tid]));
      double gv = tanh((double)s_g[128 + tid]);
      double ov = 1.0/(1.0 + exp(-(double)s_g[256 + tid]));
      s_h[tid] = (float)(ov * tanh(iv * gv));
    }
    __syncthreads();
    if (tid < 256) {
      int c = tid;
      float s = 0.f, cc = 0.f;
      #pragma unroll 8
      for (int mm = 0; mm < 128; mm++)
        kadd_(s, cc, s_h[mm] * w_fc[mm*256 + c]);
      g_fc[b*256 + c] = (s + cc) + b_fc[c];
    }
  }
  grid_barrier(NB_);

  // ================= stage E: reparam + KL on block 0 =============================
  if (blk == 0) {
    double* redd = (double*)(pool + 6144);      // 1024 doubles
    double kacc = 0.0;
    for (int idx = tid; idx < 2048; idx += 1024) {
      int bb = idx >> 7, k = idx & 127;
      float mu = g_fc[bb*256 + k];
      float lv = g_fc[bb*256 + 128 + k];
      unsigned int o0, o1;
      threefry2x32_(0u, keylo, 0u, (unsigned int)idx, o0, o1);
      unsigned int bits = o0 ^ o1;
      float f = __uint_as_float((bits >> 9) | 0x3f800000u) - 1.0f;   // [0,1)
      const float lo = -0.99999994f;                                 // nextafter(-1,0)
      float u = fmaxf(lo, fmaf(f, 2.0f, lo));
      float eps = 1.4142135623730951f * erfinvf(u);
      z_out[idx] = fmaf(eps, expf(0.5f*lv), mu);
      double dmu = (double)mu, dlv = (double)lv;
      kacc += 1.0 + dlv - dmu*dmu - exp(dlv);
    }
    redd[tid] = kacc;
    __syncthreads();
    for (int o = 512; o; o >>= 1) {
      if (tid < o) redd[tid] += redd[tid + o];
      __syncthreads();
    }
    if (tid == 0) kl_out[0] = (float)(-0.5 * redd[0] * (1.0/2048.0));
  }

  // ================= stage F: decode MLP on 16 blocks (pass 1 only) ===============
  if (do_dec) {
    grid_barrier(NB_);        // z_out visible to all blocks
    if (blk < 16) {
      float* zsm = pool;        // 128
      float* h1  = pool + 128;  // 128
      int bb = blk;
      if (tid < 128) zsm[tid] = z_out[bb*128 + tid];
      __syncthreads();
      if (tid < 128) {
        int c = tid;
        float p[4] = {0.f,0.f,0.f,0.f};
        #pragma unroll
        for (int jb = 0; jb < 4; jb++)
          #pragma unroll 8
          for (int j0 = 0; j0 < 32; j0++) {
            int j = jb*32 + j0;
            p[jb] = fmaf(zsm[j], w_d1[j*128+c], p[jb]);
          }
        h1[c] = fmaxf(((p[0]+p[1]) + (p[2]+p[3])) + b_d1[c], 0.f);
      }
      __syncthreads();
      if (tid < 128) {
        int c = tid;
        float p[4] = {0.f,0.f,0.f,0.f};
        #pragma unroll
        for (int jb = 0; jb < 4; jb++)
          #pragma unroll 8
          for (int j0 = 0; j0 < 32; j0++) {
            int j = jb*32 + j0;
            p[jb] = fmaf(h1[j], w_d2[j*128+c], p[jb]);
          }
        g_h2[bb*128 + c] = fmaxf(((p[0]+p[1]) + (p[2]+p[3])) + b_d2[c], 0.f);
      }
    }
  }
}

// ---------------- big decode GEMM h2[16,128] @ w_d3[128,262144] + b_d3 ----------------
__device__ __forceinline__ unsigned long long pk2_(float a, float b){
  return (unsigned long long)__float_as_uint(a) | ((unsigned long long)__float_as_uint(b) << 32);
}

__global__ void __launch_bounds__(256) big_kernel(
    const float* __restrict__ w_d3, const float* __restrict__ b_d3, float* __restrict__ out)
{
  __shared__ unsigned long long hp[8*128];   // (b-pair, j) packed h2 values
  int tid = threadIdx.x;
  for (int i = tid; i < 1024; i += 256) {
    int p = i >> 7, j = i & 127;
    hp[i] = pk2_(g_h2[(2*p)*128 + j], g_h2[(2*p+1)*128 + j]);
  }
  __syncthreads();
  size_t m2 = (size_t)blockIdx.x*256 + tid;    // float2 column index, < 131072
  const float2* w2 = (const float2*)w_d3;
  float2 bv2 = ((const float2*)b_d3)[m2];
  unsigned long long accx[8], accy[8];
  unsigned long long bx = pk2_(bv2.x, bv2.x), by = pk2_(bv2.y, bv2.y);
  #pragma unroll
  for (int p = 0; p < 8; p++){ accx[p] = bx; accy[p] = by; }
  #pragma unroll 4
  for (int j = 0; j < 128; j++) {
    float2 w = __ldg(&w2[(size_t)j*131072 + m2]);
    unsigned long long wx = pk2_(w.x, w.x), wy = pk2_(w.y, w.y);
    #pragma unroll
    for (int p = 0; p < 8; p++) {
      unsigned long long hpair = hp[p*128 + j];
      asm("fma.rn.f32x2 %0, %1, %2, %3;" : "=l"(accx[p]) : "l"(hpair), "l"(wx), "l"(accx[p]));
      asm("fma.rn.f32x2 %0, %1, %2, %3;" : "=l"(accy[p]) : "l"(hpair), "l"(wy), "l"(accy[p]));
    }
  }
  float2* o2 = (float2*)out;
  #pragma unroll
  for (int p = 0; p < 8; p++) {
    float2 v0, v1;
    v0.x = __uint_as_float((unsigned int)accx[p]);
    v0.y = __uint_as_float((unsigned int)accy[p]);
    v1.x = __uint_as_float((unsigned int)(accx[p] >> 32));
    v1.y = __uint_as_float((unsigned int)(accy[p] >> 32));
    o2[(size_t)(2*p)*131072 + m2]   = v0;
    o2[(size_t)(2*p+1)*131072 + m2] = v1;
  }
}

// ---------------- launcher (3 launches total) ----------------
extern "C" void kernel_launch(void* const* d_in, const int* in_sizes, int n_in,
                              void* d_out, int out_size)
{
  (void)in_sizes; (void)n_in; (void)out_size;
  const float* x     = (const float*)d_in[0];
  const float* w_enc = (const float*)d_in[1];
  const float* b_enc = (const float*)d_in[2];
  const float* wq    = (const float*)d_in[3];
  const float* bq    = (const float*)d_in[4];
  const float* wk    = (const float*)d_in[5];
  const float* bk    = (const float*)d_in[6];
  const float* wv    = (const float*)d_in[7];
  const float* bv    = (const float*)d_in[8];
  const float* W_ii  = (const float*)d_in[9];
  const float* W_ig  = (const float*)d_in[13];
  const float* W_io  = (const float*)d_in[15];
  const float* w_fc  = (const float*)d_in[17];
  const float* b_fc  = (const float*)d_in[18];
  const float* w_d1  = (const float*)d_in[19];
  const float* b_d1  = (const float*)d_in[20];
  const float* w_d2  = (const float*)d_in[21];
  const float* b_d2  = (const float*)d_in[22];
  const float* w_d3  = (const float*)d_in[23];
  const float* b_d3  = (const float*)d_in[24];

  float* outp = (float*)d_out;
  float* xhat = outp;                  // [16,64,32,128] = 4194304
  float* z1   = outp + 4194304;        // [16,128]
  float* z2   = z1 + 2048;             // [16,128]
  float* kl1  = z2 + 2048;             // scalar
  float* kl2  = kl1 + 1;               // scalar

  // -------- pass 1: encode(x, key=1) + decode MLP --------
  enc_kernel<<<NB_, 1024>>>(x, w_enc, b_enc, wq, bq, wk, bk, wv, bv,
                            W_ii, W_ig, W_io, w_fc, b_fc,
                            1u, z1, kl1, 1, w_d1, b_d1, w_d2, b_d2);
  // -------- big decode GEMM --------
  big_kernel<<<512, 256>>>(w_d3, b_d3, xhat);
  // -------- pass 2: encode(x_hat1, key=2) --------
  enc_kernel<<<NB_, 1024>>>(xhat, w_enc, b_enc, wq, bq, wk, bk, wv, bv,
                            W_ii, W_ig, W_io, w_fc, b_fc,
                            2u, z2, kl2, 0, w_d1, b_d1, w_d2, b_d2);
}

// round 15
// speedup vs baseline: 2.6697x; 1.2087x over previous
#include <cuda_runtime.h>
#include <math.h>

// Problem dims
#define BB_ 16
#define T_ 64
#define S_ 32
#define F_ 128
#define H_ 128
#define NH_ 4

// ---------------- scratch (no allocations allowed) ----------------
__device__ float g_hid[BB_*H_*S_];       // 65536  hid (t=T-1), computed once
__device__ float g_att4[BB_*NH_*H_*S_];  // attention outputs (pre head-mean)
__device__ float g_part[3*32*BB_*H_];    // gate split-K partials
__device__ float g_h2[BB_*H_];           // decoder h2
__device__ double g_partKL[BB_];         // per-batch KL partials

// barrier state
__device__ unsigned int g_cnt = 0;
__device__ unsigned int g_gen = 0;
__device__ unsigned int g_klcnt = 0;

#define NB_ 128

// ---- fence-free acquire/release primitives (gpu scope) ----
__device__ __forceinline__ unsigned int ld_acq_(unsigned int* p){
  unsigned int v;
  asm volatile("ld.acquire.gpu.global.u32 %0, [%1];" : "=r"(v) : "l"(p) : "memory");
  return v;
}
__device__ __forceinline__ unsigned int atom_add_acqrel_(unsigned int* p, unsigned int v){
  unsigned int old;
  asm volatile("atom.acq_rel.gpu.global.add.u32 %0, [%1], %2;" : "=r"(old) : "l"(p), "r"(v) : "memory");
  return old;
}
__device__ __forceinline__ void st_rel_(unsigned int* p, unsigned int v){
  asm volatile("st.release.gpu.global.u32 [%0], %1;" :: "l"(p), "r"(v) : "memory");
}
__device__ __forceinline__ void st_rlx_(unsigned int* p, unsigned int v){
  asm volatile("st.relaxed.gpu.global.u32 [%0], %1;" :: "l"(p), "r"(v) : "memory");
}

// Grid barrier: release-arrive + acquire-poll; no gpu-scope fence (no L1 flush).
// wait=false: arrive only (block may exit afterwards).
__device__ __forceinline__ void grid_barrier(int nb, bool wait){
  __syncthreads();
  if (threadIdx.x == 0) {
    unsigned int gen = ld_acq_(&g_gen);
    unsigned int old = atom_add_acqrel_(&g_cnt, 1u);
    if (old == (unsigned int)nb - 1u) {
      st_rlx_(&g_cnt, 0u);
      st_rel_(&g_gen, gen + 1u);
    } else if (wait) {
      while (ld_acq_(&g_gen) == gen) { }
    }
  }
  __syncthreads();
}

__device__ __forceinline__ unsigned int rotl32_(unsigned int v, int d){ return (v << d) | (v >> (32 - d)); }

// Neumaier compensated accumulate (kept in the cheap, KL-sensitive tail).
__device__ __forceinline__ void kadd_(float& s, float& c, float p){
  float t = s + p;
  c += (fabsf(s) >= fabsf(p)) ? ((s - t) + p) : ((p - t) + s);
  s = t;
}

// Exact JAX threefry2x32 (20 rounds), key = (k0, k1)
__device__ __forceinline__ void threefry2x32_(unsigned int k0, unsigned int k1,
    unsigned int c0, unsigned int c1, unsigned int& o0, unsigned int& o1)
{
  unsigned int ks2 = k0 ^ k1 ^ 0x1BD11BDAu;
  unsigned int x0 = c0 + k0, x1 = c1 + k1;
  const int ra[4] = {13,15,26,6};
  const int rb[4] = {17,29,16,24};
  #pragma unroll
  for (int i=0;i<4;i++){ x0 += x1; x1 = rotl32_(x1, ra[i]); x1 ^= x0; }
  x0 += k1; x1 += ks2 + 1u;
  #pragma unroll
  for (int i=0;i<4;i++){ x0 += x1; x1 = rotl32_(x1, rb[i]); x1 ^= x0; }
  x0 += ks2; x1 += k0 + 2u;
  #pragma unroll
  for (int i=0;i<4;i++){ x0 += x1; x1 = rotl32_(x1, ra[i]); x1 ^= x0; }
  x0 += k0; x1 += k1 + 3u;
  #pragma unroll
  for (int i=0;i<4;i++){ x0 += x1; x1 = rotl32_(x1, rb[i]); x1 ^= x0; }
  x0 += k1; x1 += ks2 + 4u;
  #pragma unroll
  for (int i=0;i<4;i++){ x0 += x1; x1 = rotl32_(x1, ra[i]); x1 ^= x0; }
  x0 += ks2; x1 += k0 + 5u;
  o0 = x0; o1 = x1;
}

// ---------------- fused encoder pass, 128 co-resident blocks x 1024 threads ---------
__global__ void __launch_bounds__(1024) enc_kernel(
    const float* __restrict__ xsrc,
    const float* __restrict__ w_enc, const float* __restrict__ b_enc,
    const float* __restrict__ wq, const float* __restrict__ bq,
    const float* __restrict__ wk, const float* __restrict__ bk,
    const float* __restrict__ wv, const float* __restrict__ bv,
    const float* __restrict__ Wii, const float* __restrict__ Wig, const float* __restrict__ Wio,
    const float* __restrict__ w_fc, const float* __restrict__ b_fc,
    unsigned int keylo, float* __restrict__ z_out, float* __restrict__ kl_out,
    int do_dec,
    const float* __restrict__ w_d1, const float* __restrict__ b_d1,
    const float* __restrict__ w_d2, const float* __restrict__ b_d2)
{
  // pool (floats): AB: [0..4127] kT[32][129]; [4128..8223] v[128][32];
  // [8224..10271] q[64][32]; [10272..11295] wk_sm[32][32]
  __shared__ __align__(16) float pool[11296];
  int blk = blockIdx.x, tid = threadIdx.x;
  int warp = tid >> 5, lane = tid & 31;

  // ================= stage A0: hid once per (b, ht of 16 rows), split-F ============
  // Tree ((p0+p1)+(p2+p3))+b_enc identical to R14; halves (f0..63) / (f64..127)
  // computed by thread pairs and combined in that exact order.
  {
    float* xs = pool;            // 4128
    float* ps = pool + 8192;     // 512 partials from the hi half
    int b = blk >> 3, ht = blk & 7;
    const float* xb = xsrc + (size_t)b*(T_*S_*F_) + (size_t)(T_-1)*(S_*F_);
    for (int i = tid; i < 4096; i += 1024)
      xs[(i>>7)*129 + (i&127)] = xb[i];
    __syncthreads();
    int s = tid & 31, hl = (tid >> 5) & 15, hi = tid >> 9;  // hi = f-half
    int h = ht*16 + hl;
    float pa = 0.f, pb = 0.f;
    #pragma unroll
    for (int fb2 = 0; fb2 < 2; fb2++) {
      float p = 0.f;
      #pragma unroll 8
      for (int f0 = 0; f0 < 32; f0++) {
        int f = (hi*2 + fb2)*32 + f0;
        p = fmaf(xs[s*129+f], w_enc[(size_t)f*H_ + h], p);
      }
      if (fb2 == 0) pa = p; else pb = p;
    }
    float halfsum = pa + pb;
    if (hi) ps[tid - 512] = halfsum;
    __syncthreads();
    if (!hi)
      g_hid[b*(H_*S_) + h*S_ + s] = (halfsum + ps[tid]) + b_enc[h];
  }
  grid_barrier(NB_, true);

  // ================= stage AB: qkv + attention, one (b,n,half) unit per block ======
  {
    float* kT   = pool;            // kT[s*129+g]
    float* vsm  = pool + 4128;
    float* qsm  = pool + 8224;
    float* wksm = pool + 10272;
    int b = blk >> 3, n = (blk >> 1) & 3, half = blk & 1;
    wksm[tid & 1023] = wk[((tid & 1023)>>5)*(S_*NH_) + n*S_ + (tid&31)];
    float hid_r[4];
    #pragma unroll
    for (int rr = 0; rr < 4; rr++)
      hid_r[rr] = g_hid[b*(H_*S_) + (warp*4+rr)*S_ + lane];
    __syncthreads();

    const float scale = 0.08838834764831845f; // 1/sqrt(H)
    bool doq = (warp >= half*16) && (warp < half*16 + 16);
    float accK[4] = {0.f,0.f,0.f,0.f};
    float accV[4] = {0.f,0.f,0.f,0.f};
    float accQ[4] = {0.f,0.f,0.f,0.f};
    #pragma unroll 4
    for (int sp = 0; sp < 32; sp++) {
      float wkv = wksm[sp*32 + lane];
      float wqv = __ldg(wq + sp*(S_*NH_) + n*S_ + lane);
      float wvv = __ldg(wv + sp*(S_*NH_) + n*S_ + lane);
      #pragma unroll
      for (int rr = 0; rr < 4; rr++) {
        float hv = __shfl_sync(0xffffffffu, hid_r[rr], sp);
        accK[rr] = fmaf(hv, wkv, accK[rr]);
        accV[rr] = fmaf(hv, wvv, accV[rr]);
        if (doq) accQ[rr] = fmaf(hv, wqv, accQ[rr]);
      }
    }
    #pragma unroll
    for (int rr = 0; rr < 4; rr++) {
      int h = warp*4 + rr;
      kT[lane*129 + h] = accK[rr] + bk[n*S_+lane];
      vsm[h*32 + lane] = accV[rr] + bv[n*S_+lane];
      if (doq)
        qsm[(h - half*64)*32 + lane] = (accQ[rr] + bq[n*S_+lane]) * scale;
    }
    __syncthreads();

    size_t base = ((size_t)(b*NH_ + n))*(H_*S_);
    float q_reg[2];
    #pragma unroll
    for (int r = 0; r < 2; r++) q_reg[r] = qsm[(warp*2 + r)*32 + lane];

    float lg[2][4];
    #pragma unroll
    for (int r = 0; r < 2; r++)
      #pragma unroll
      for (int j = 0; j < 4; j++) lg[r][j] = 0.f;
    #pragma unroll 8
    for (int s = 0; s < 32; s++) {
      float kv0 = kT[s*129 + lane];
      float kv1 = kT[s*129 + lane + 32];
      float kv2 = kT[s*129 + lane + 64];
      float kv3 = kT[s*129 + lane + 96];
      #pragma unroll
      for (int r = 0; r < 2; r++) {
        float qv = __shfl_sync(0xffffffffu, q_reg[r], s);
        lg[r][0] = fmaf(qv, kv0, lg[r][0]);
        lg[r][1] = fmaf(qv, kv1, lg[r][1]);
        lg[r][2] = fmaf(qv, kv2, lg[r][2]);
        lg[r][3] = fmaf(qv, kv3, lg[r][3]);
      }
    }
    #pragma unroll
    for (int r = 0; r < 2; r++) {
      float m = fmaxf(fmaxf(lg[r][0],lg[r][1]), fmaxf(lg[r][2],lg[r][3]));
      #pragma unroll
      for (int o = 16; o; o >>= 1) m = fmaxf(m, __shfl_xor_sync(0xffffffffu, m, o));
      float ssum = 0.f;
      #pragma unroll
      for (int j = 0; j < 4; j++){ lg[r][j] = expf(lg[r][j]-m); ssum += lg[r][j]; }
      #pragma unroll
      for (int o = 16; o; o >>= 1) ssum += __shfl_xor_sync(0xffffffffu, ssum, o);
      float inv = 1.f/ssum;
      #pragma unroll
      for (int j = 0; j < 4; j++) lg[r][j] *= inv;
    }
    float accP[2][4];
    #pragma unroll
    for (int r = 0; r < 2; r++)
      #pragma unroll
      for (int gb = 0; gb < 4; gb++) accP[r][gb] = 0.f;
    #pragma unroll
    for (int gb = 0; gb < 4; gb++) {
      #pragma unroll 8
      for (int g0 = 0; g0 < 32; g0++) {
        int g = gb*32 + g0;
        float vv = vsm[g*32 + lane];
        #pragma unroll
        for (int r = 0; r < 2; r++) {
          float pwv = __shfl_sync(0xffffffffu, lg[r][gb], g0);
          accP[r][gb] = fmaf(pwv, vv, accP[r][gb]);
        }
      }
    }
    #pragma unroll
    for (int r = 0; r < 2; r++) {
      float acc = (accP[r][0]+accP[r][1]) + (accP[r][2]+accP[r][3]);
      g_att4[base + (size_t)(half*64 + warp*2 + r)*S_ + lane] = acc;
    }
  }
  grid_barrier(NB_, true);

  // ================= stage C: gate GEMM (fused head-mean+ReLU) ====================
  if (blk < 96) {
    float* as = pool;   // 16*128
    int gate = blk / 32, chunk = blk & 31;
    const float* Wm = (gate == 0) ? Wii : (gate == 1) ? Wig : Wio;
    int j0 = chunk*128;
    for (int i = tid; i < 16*128; i += 1024) {
      int bb = i >> 7, j = i & 127;
      size_t bbase = (size_t)bb*4*(H_*S_);
      int hs = j0 + j;
      float v = (g_att4[bbase + hs] + g_att4[bbase + 4096 + hs])
              + (g_att4[bbase + 8192 + hs] + g_att4[bbase + 12288 + hs]);
      v *= 0.25f;
      as[i] = v > 0.f ? v : 0.f;
    }
    __syncthreads();
    int m = tid & 127, oct = tid >> 7;   // oct 0..7, 2 batch rows each
    float acc[2][4];
    #pragma unroll
    for (int bbi = 0; bbi < 2; bbi++)
      #pragma unroll
      for (int jb = 0; jb < 4; jb++) acc[bbi][jb] = 0.f;
    #pragma unroll
    for (int jb = 0; jb < 4; jb++)
      #pragma unroll 8
      for (int j0i = 0; j0i < 32; j0i++) {
        int j = jb*32 + j0i;
        float w = Wm[(size_t)(j0+j)*H_ + m];
        #pragma unroll
        for (int bbi = 0; bbi < 2; bbi++)
          acc[bbi][jb] = fmaf(as[(oct*2+bbi)*128 + j], w, acc[bbi][jb]);
      }
    size_t cbase = ((size_t)(gate*32 + chunk))*(BB_*H_);
    #pragma unroll
    for (int bbi = 0; bbi < 2; bbi++)
      g_part[cbase + (oct*2+bbi)*H_ + m] =
        (acc[bbi][0]+acc[bbi][1]) + (acc[bbi][2]+acc[bbi][3]);
  }

  // barrier 3: blocks >= 16 arrive and exit; 0..15 continue to stage D'
  if (blk >= 16) { grid_barrier(NB_, false); return; }
  grid_barrier(NB_, true);

  // ================= stage D': per-b tail — reduce+LSTM+fc+reparam+KL(+dec) =======
  {
    float* s_g  = pool;          // 384
    float* s_h  = pool + 512;    // 128
    float* s_fc = pool + 768;    // 256
    float* s_z  = pool + 1024;   // 128
    float* h1   = pool + 1280;   // 128
    double* rd  = (double*)(pool + 2048);  // 128 doubles
    int b = blk;
    if (tid < 384) {
      int gate = tid >> 7, m = tid & 127;
      int r = b*128 + m;
      float s = 0.f, c = 0.f;
      #pragma unroll
      for (int ch = 0; ch < 32; ch++)
        kadd_(s, c, g_part[(size_t)(gate*32 + ch)*(BB_*H_) + r]);
      s_g[gate*128 + m] = s + c;
    }
    __syncthreads();
    if (tid < 128) {
      double iv = 1.0/(1.0 + exp(-(double)s_g[tid]));
      double gv = tanh((double)s_g[128 + tid]);
      double ov = 1.0/(1.0 + exp(-(double)s_g[256 + tid]));
      s_h[tid] = (float)(ov * tanh(iv * gv));
    }
    __syncthreads();
    if (tid < 256) {
      int c = tid;
      float s = 0.f, cc = 0.f;
      #pragma unroll 8
      for (int mm = 0; mm < 128; mm++)
        kadd_(s, cc, s_h[mm] * w_fc[mm*256 + c]);
      s_fc[c] = (s + cc) + b_fc[c];
    }
    __syncthreads();
    if (tid < 128) {
      int k = tid, idx = b*128 + k;
      float mu = s_fc[k];
      float lv = s_fc[128 + k];
      unsigned int o0, o1;
      threefry2x32_(0u, keylo, 0u, (unsigned int)idx, o0, o1);
      unsigned int bits = o0 ^ o1;
      float f = __uint_as_float((bits >> 9) | 0x3f800000u) - 1.0f;   // [0,1)
      const float lo = -0.99999994f;                                 // nextafter(-1,0)
      float u = fmaxf(lo, fmaf(f, 2.0f, lo));
      float eps = 1.4142135623730951f * erfinvf(u);
      float zv = fmaf(eps, expf(0.5f*lv), mu);
      z_out[idx] = zv;
      s_z[k] = zv;
      double dmu = (double)mu, dlv = (double)lv;
      rd[k] = 1.0 + dlv - dmu*dmu - exp(dlv);
    }
    __syncthreads();
    for (int o = 64; o; o >>= 1) {
      if (tid < o) rd[tid] += rd[tid + o];
      __syncthreads();
    }
    if (tid == 0) g_partKL[b] = rd[0];
    __syncthreads();
    if (b != 0 && tid == 0)
      atom_add_acqrel_(&g_klcnt, 1u);   // release partial KL

    if (do_dec) {
      if (tid < 128) {
        int c = tid;
        float p[4] = {0.f,0.f,0.f,0.f};
        #pragma unroll
        for (int jb = 0; jb < 4; jb++)
          #pragma unroll 8
          for (int j0 = 0; j0 < 32; j0++) {
            int j = jb*32 + j0;
            p[jb] = fmaf(s_z[j], w_d1[j*128+c], p[jb]);
          }
        h1[c] = fmaxf(((p[0]+p[1]) + (p[2]+p[3])) + b_d1[c], 0.f);
      }
      __syncthreads();
      if (tid < 128) {
        int c = tid;
        float p[4] = {0.f,0.f,0.f,0.f};
        #pragma unroll
        for (int jb = 0; jb < 4; jb++)
          #pragma unroll 8
          for (int j0 = 0; j0 < 32; j0++) {
            int j = jb*32 + j0;
            p[jb] = fmaf(h1[j], w_d2[j*128+c], p[jb]);
          }
        g_h2[b*128 + c] = fmaxf(((p[0]+p[1]) + (p[2]+p[3])) + b_d2[c], 0.f);
      }
    }

    // block 0 finalizes KL after all 15 partners arrive
    if (b == 0 && tid == 0) {
      while (ld_acq_(&g_klcnt) < 15u) { }
      double ks = 0.0;
      #pragma unroll
      for (int b2 = 0; b2 < 16; b2++) ks += g_partKL[b2];
      kl_out[0] = (float)(-0.5 * ks * (1.0/2048.0));
      st_rlx_(&g_klcnt, 0u);
    }
  }
}

// ---------------- big decode GEMM h2[16,128] @ w_d3[128,262144] + b_d3 ----------------
__device__ __forceinline__ unsigned long long pk2_(float a, float b){
  return (unsigned long long)__float_as_uint(a) | ((unsigned long long)__float_as_uint(b) << 32);
}

__global__ void __launch_bounds__(256) big_kernel(
    const float* __restrict__ w_d3, const float* __restrict__ b_d3, float* __restrict__ out)
{
  __shared__ unsigned long long hp[8*128];   // (b-pair, j) packed h2 values
  int tid = threadIdx.x;
  for (int i = tid; i < 1024; i += 256) {
    int p = i >> 7, j = i & 127;
    hp[i] = pk2_(g_h2[(2*p)*128 + j], g_h2[(2*p+1)*128 + j]);
  }
  __syncthreads();
  size_t m2 = (size_t)blockIdx.x*256 + tid;    // float2 column index, < 131072
  const float2* w2 = (const float2*)w_d3;
  float2 bv2 = ((const float2*)b_d3)[m2];
  unsigned long long accx[8], accy[8];
  unsigned long long bx = pk2_(bv2.x, bv2.x), by = pk2_(bv2.y, bv2.y);
  #pragma unroll
  for (int p = 0; p < 8; p++){ accx[p] = bx; accy[p] = by; }
  #pragma unroll 4
  for (int j = 0; j < 128; j++) {
    float2 w = __ldg(&w2[(size_t)j*131072 + m2]);
    unsigned long long wx = pk2_(w.x, w.x), wy = pk2_(w.y, w.y);
    #pragma unroll
    for (int p = 0; p < 8; p++) {
      unsigned long long hpair = hp[p*128 + j];
      asm("fma.rn.f32x2 %0, %1, %2, %3;" : "=l"(accx[p]) : "l"(hpair), "l"(wx), "l"(accx[p]));
      asm("fma.rn.f32x2 %0, %1, %2, %3;" : "=l"(accy[p]) : "l"(hpair), "l"(wy), "l"(accy[p]));
    }
  }
  float2* o2 = (float2*)out;
  #pragma unroll
  for (int p = 0; p < 8; p++) {
    float2 v0, v1;
    v0.x = __uint_as_float((unsigned int)accx[p]);
    v0.y = __uint_as_float((unsigned int)accy[p]);
    v1.x = __uint_as_float((unsigned int)(accx[p] >> 32));
    v1.y = __uint_as_float((unsigned int)(accy[p] >> 32));
    o2[(size_t)(2*p)*131072 + m2]   = v0;
    o2[(size_t)(2*p+1)*131072 + m2] = v1;
  }
}

// ---------------- launcher (3 launches total) ----------------
extern "C" void kernel_launch(void* const* d_in, const int* in_sizes, int n_in,
                              void* d_out, int out_size)
{
  (void)in_sizes; (void)n_in; (void)out_size;
  const float* x     = (const float*)d_in[0];
  const float* w_enc = (const float*)d_in[1];
  const float* b_enc = (const float*)d_in[2];
  const float* wq    = (const float*)d_in[3];
  const float* bq    = (const float*)d_in[4];
  const float* wk    = (const float*)d_in[5];
  const float* bk    = (const float*)d_in[6];
  const float* wv    = (const float*)d_in[7];
  const float* bv    = (const float*)d_in[8];
  const float* W_ii  = (const float*)d_in[9];
  const float* W_ig  = (const float*)d_in[13];
  const float* W_io  = (const float*)d_in[15];
  const float* w_fc  = (const float*)d_in[17];
  const float* b_fc  = (const float*)d_in[18];
  const float* w_d1  = (const float*)d_in[19];
  const float* b_d1  = (const float*)d_in[20];
  const float* w_d2  = (const float*)d_in[21];
  const float* b_d2  = (const float*)d_in[22];
  const float* w_d3  = (const float*)d_in[23];
  const float* b_d3  = (const float*)d_in[24];

  float* outp = (float*)d_out;
  float* xhat = outp;                  // [16,64,32,128] = 4194304
  float* z1   = outp + 4194304;        // [16,128]
  float* z2   = z1 + 2048;             // [16,128]
  float* kl1  = z2 + 2048;             // scalar
  float* kl2  = kl1 + 1;               // scalar

  // -------- pass 1: encode(x, key=1) + decode MLP --------
  enc_kernel<<<NB_, 1024>>>(x, w_enc, b_enc, wq, bq, wk, bk, wv, bv,
                            W_ii, W_ig, W_io, w_fc, b_fc,
                            1u, z1, kl1, 1, w_d1, b_d1, w_d2, b_d2);
  // -------- big decode GEMM --------
  big_kernel<<<512, 256>>>(w_d3, b_d3, xhat);
  // -------- pass 2: encode(x_hat1, key=2) --------
  enc_kernel<<<NB_, 1024>>>(xhat, w_enc, b_enc, wq, bq, wk, bk, wv, bv,
                            W_ii, W_ig, W_io, w_fc, b_fc,
                            2u, z2, kl2, 0, w_d1, b_d1, w_d2, b_d2);
}

// round 16
// speedup vs baseline: 2.8854x; 1.0808x over previous
#include <cuda_runtime.h>
#include <math.h>

// Problem dims
#define BB_ 16
#define T_ 64
#define S_ 32
#define F_ 128
#define H_ 128
#define NH_ 4

// ---------------- scratch (no allocations allowed) ----------------
__device__ float g_hid[BB_*H_*S_];       // 65536  hid (t=T-1), computed once
__device__ float g_att4[BB_*NH_*H_*S_];  // attention outputs (pre head-mean)
__device__ float g_part[3*32*BB_*H_];    // gate split-K partials
__device__ float g_h2[BB_*H_];           // decoder h2
__device__ double g_partKL[BB_];         // per-batch KL partials

// barrier state
__device__ unsigned int g_cnt = 0;
__device__ unsigned int g_gen = 0;
__device__ unsigned int g_klcnt = 0;
__device__ unsigned int g_bcnt[BB_];     // per-batch A0->AB mini-barrier

#define NB_ 128

// ---- fence-free acquire/release primitives (gpu scope) ----
__device__ __forceinline__ unsigned int ld_acq_(unsigned int* p){
  unsigned int v;
  asm volatile("ld.acquire.gpu.global.u32 %0, [%1];" : "=r"(v) : "l"(p) : "memory");
  return v;
}
__device__ __forceinline__ unsigned int atom_add_acqrel_(unsigned int* p, unsigned int v){
  unsigned int old;
  asm volatile("atom.acq_rel.gpu.global.add.u32 %0, [%1], %2;" : "=r"(old) : "l"(p), "r"(v) : "memory");
  return old;
}
__device__ __forceinline__ void st_rel_(unsigned int* p, unsigned int v){
  asm volatile("st.release.gpu.global.u32 [%0], %1;" :: "l"(p), "r"(v) : "memory");
}
__device__ __forceinline__ void st_rlx_(unsigned int* p, unsigned int v){
  asm volatile("st.relaxed.gpu.global.u32 [%0], %1;" :: "l"(p), "r"(v) : "memory");
}

// Grid barrier: release-arrive + acquire-poll; no gpu-scope fence (no L1 flush).
__device__ __forceinline__ void grid_barrier(int nb, bool wait){
  __syncthreads();
  if (threadIdx.x == 0) {
    unsigned int gen = ld_acq_(&g_gen);
    unsigned int old = atom_add_acqrel_(&g_cnt, 1u);
    if (old == (unsigned int)nb - 1u) {
      st_rlx_(&g_cnt, 0u);
      st_rel_(&g_gen, gen + 1u);
    } else if (wait) {
      while (ld_acq_(&g_gen) == gen) { }
    }
  }
  __syncthreads();
}

__device__ __forceinline__ unsigned int rotl32_(unsigned int v, int d){ return (v << d) | (v >> (32 - d)); }

// Neumaier compensated accumulate (kept in the cheap, KL-sensitive tail).
__device__ __forceinline__ void kadd_(float& s, float& c, float p){
  float t = s + p;
  c += (fabsf(s) >= fabsf(p)) ? ((s - t) + p) : ((p - t) + s);
  s = t;
}

// Exact JAX threefry2x32 (20 rounds), key = (k0, k1)
__device__ __forceinline__ void threefry2x32_(unsigned int k0, unsigned int k1,
    unsigned int c0, unsigned int c1, unsigned int& o0, unsigned int& o1)
{
  unsigned int ks2 = k0 ^ k1 ^ 0x1BD11BDAu;
  unsigned int x0 = c0 + k0, x1 = c1 + k1;
  const int ra[4] = {13,15,26,6};
  const int rb[4] = {17,29,16,24};
  #pragma unroll
  for (int i=0;i<4;i++){ x0 += x1; x1 = rotl32_(x1, ra[i]); x1 ^= x0; }
  x0 += k1; x1 += ks2 + 1u;
  #pragma unroll
  for (int i=0;i<4;i++){ x0 += x1; x1 = rotl32_(x1, rb[i]); x1 ^= x0; }
  x0 += ks2; x1 += k0 + 2u;
  #pragma unroll
  for (int i=0;i<4;i++){ x0 += x1; x1 = rotl32_(x1, ra[i]); x1 ^= x0; }
  x0 += k0; x1 += k1 + 3u;
  #pragma unroll
  for (int i=0;i<4;i++){ x0 += x1; x1 = rotl32_(x1, rb[i]); x1 ^= x0; }
  x0 += k1; x1 += ks2 + 4u;
  #pragma unroll
  for (int i=0;i<4;i++){ x0 += x1; x1 = rotl32_(x1, ra[i]); x1 ^= x0; }
  x0 += ks2; x1 += k0 + 5u;
  o0 = x0; o1 = x1;
}

// ---------------- fused encoder pass, 128 co-resident blocks x 1024 threads ---------
__global__ void __launch_bounds__(1024) enc_kernel(
    const float* __restrict__ xsrc,
    const float* __restrict__ w_enc, const float* __restrict__ b_enc,
    const float* __restrict__ wq, const float* __restrict__ bq,
    const float* __restrict__ wk, const float* __restrict__ bk,
    const float* __restrict__ wv, const float* __restrict__ bv,
    const float* __restrict__ Wii, const float* __restrict__ Wig, const float* __restrict__ Wio,
    const float* __restrict__ w_fc, const float* __restrict__ b_fc,
    unsigned int keylo, float* __restrict__ z_out, float* __restrict__ kl_out,
    int do_dec,
    const float* __restrict__ w_d1, const float* __restrict__ b_d1,
    const float* __restrict__ w_d2, const float* __restrict__ b_d2)
{
  // pool (floats), phased:
  //  A0:    xs[0..4127], ps[8192..8703]
  //  AB-p1: hsm[0..4095], wksm[4096..5119], wqsm[5120..6143], wvsm[6144..7167]
  //  AB-p2: kT[0..4127], vsm[4128..8223], qsm[8224..10271]
  __shared__ __align__(16) float pool[10272];
  int blk = blockIdx.x, tid = threadIdx.x;
  int warp = tid >> 5, lane = tid & 31;

  // ================= stage A0: hid once per (b, ht of 16 rows), split-F ============
  {
    float* xs = pool;            // 4128
    float* ps = pool + 8192;     // 512 partials from the hi half
    int b = blk >> 3, ht = blk & 7;
    const float* xb = xsrc + (size_t)b*(T_*S_*F_) + (size_t)(T_-1)*(S_*F_);
    for (int i = tid; i < 4096; i += 1024)
      xs[(i>>7)*129 + (i&127)] = xb[i];
    __syncthreads();
    int s = tid & 31, hl = (tid >> 5) & 15, hi = tid >> 9;  // hi = f-half
    int h = ht*16 + hl;
    float pa = 0.f, pb = 0.f;
    #pragma unroll
    for (int fb2 = 0; fb2 < 2; fb2++) {
      float p = 0.f;
      #pragma unroll 8
      for (int f0 = 0; f0 < 32; f0++) {
        int f = (hi*2 + fb2)*32 + f0;
        p = fmaf(xs[s*129+f], w_enc[(size_t)f*H_ + h], p);
      }
      if (fb2 == 0) pa = p; else pb = p;
    }
    float halfsum = pa + pb;
    if (hi) ps[tid - 512] = halfsum;
    __syncthreads();
    if (!hi)
      g_hid[b*(H_*S_) + h*S_ + s] = (halfsum + ps[tid]) + b_enc[h];
    // arrive on this batch's mini-barrier (release)
    __syncthreads();
    if (tid == 0) atom_add_acqrel_(&g_bcnt[b], 1u);
  }

  // ================= stage AB: qkv + attention, one (b,n,half) unit per block ======
  {
    float* hsm  = pool;            // phase 1
    float* wksm = pool + 4096;
    float* wqsm = pool + 5120;
    float* wvsm = pool + 6144;
    float* kT   = pool;            // phase 2 (kT[s*129+g])
    float* vsm  = pool + 4128;
    float* qsm  = pool + 8224;
    int b = blk >> 3, n = (blk >> 1) & 3, half = blk & 1;

    // mini-barrier: wait for this batch's 8 A0 producers (acquire)
    if (tid == 0) { while (ld_acq_(&g_bcnt[b]) < 8u) { } }
    __syncthreads();

    for (int i = tid; i < 4096; i += 1024)
      hsm[i] = g_hid[b*(H_*S_) + i];      // identical linear layout [h*32+s]
    {
      int rw = tid >> 5, cl = tid & 31;
      wksm[tid] = wk[rw*(S_*NH_) + n*S_ + cl];
      wqsm[tid] = wq[rw*(S_*NH_) + n*S_ + cl];
      wvsm[tid] = wv[rw*(S_*NH_) + n*S_ + cl];
    }
    __syncthreads();

    const float scale = 0.08838834764831845f; // 1/sqrt(H)
    bool doq = (warp >= half*16) && (warp < half*16 + 16);
    float accK[4] = {0.f,0.f,0.f,0.f};
    float accV[4] = {0.f,0.f,0.f,0.f};
    float accQ[4] = {0.f,0.f,0.f,0.f};
    #pragma unroll 4
    for (int sp = 0; sp < 32; sp++) {
      float wkv = wksm[sp*32 + lane];
      float wqv = wqsm[sp*32 + lane];
      float wvv = wvsm[sp*32 + lane];
      #pragma unroll
      for (int rr = 0; rr < 4; rr++) {
        float hv = hsm[(warp*4+rr)*32 + sp];   // broadcast
        accK[rr] = fmaf(hv, wkv, accK[rr]);
        accV[rr] = fmaf(hv, wvv, accV[rr]);
        if (doq) accQ[rr] = fmaf(hv, wqv, accQ[rr]);
      }
    }
    __syncthreads();   // phase-1 smem dead
    #pragma unroll
    for (int rr = 0; rr < 4; rr++) {
      int h = warp*4 + rr;
      kT[lane*129 + h] = accK[rr] + bk[n*S_+lane];
      vsm[h*32 + lane] = accV[rr] + bv[n*S_+lane];
      if (doq)
        qsm[(h - half*64)*32 + lane] = (accQ[rr] + bq[n*S_+lane]) * scale;
    }
    __syncthreads();

    size_t base = ((size_t)(b*NH_ + n))*(H_*S_);
    float q_reg[2];
    #pragma unroll
    for (int r = 0; r < 2; r++) q_reg[r] = qsm[(warp*2 + r)*32 + lane];

    float lg[2][4];
    #pragma unroll
    for (int r = 0; r < 2; r++)
      #pragma unroll
      for (int j = 0; j < 4; j++) lg[r][j] = 0.f;
    #pragma unroll 8
    for (int s = 0; s < 32; s++) {
      float kv0 = kT[s*129 + lane];
      float kv1 = kT[s*129 + lane + 32];
      float kv2 = kT[s*129 + lane + 64];
      float kv3 = kT[s*129 + lane + 96];
      #pragma unroll
      for (int r = 0; r < 2; r++) {
        float qv = __shfl_sync(0xffffffffu, q_reg[r], s);
        lg[r][0] = fmaf(qv, kv0, lg[r][0]);
        lg[r][1] = fmaf(qv, kv1, lg[r][1]);
        lg[r][2] = fmaf(qv, kv2, lg[r][2]);
        lg[r][3] = fmaf(qv, kv3, lg[r][3]);
      }
    }
    #pragma unroll
    for (int r = 0; r < 2; r++) {
      float m = fmaxf(fmaxf(lg[r][0],lg[r][1]), fmaxf(lg[r][2],lg[r][3]));
      #pragma unroll
      for (int o = 16; o; o >>= 1) m = fmaxf(m, __shfl_xor_sync(0xffffffffu, m, o));
      float ssum = 0.f;
      #pragma unroll
      for (int j = 0; j < 4; j++){ lg[r][j] = expf(lg[r][j]-m); ssum += lg[r][j]; }
      #pragma unroll
      for (int o = 16; o; o >>= 1) ssum += __shfl_xor_sync(0xffffffffu, ssum, o);
      float inv = 1.f/ssum;
      #pragma unroll
      for (int j = 0; j < 4; j++) lg[r][j] *= inv;
    }
    float accP[2][4];
    #pragma unroll
    for (int r = 0; r < 2; r++)
      #pragma unroll
      for (int gb = 0; gb < 4; gb++) accP[r][gb] = 0.f;
    #pragma unroll
    for (int gb = 0; gb < 4; gb++) {
      #pragma unroll 8
      for (int g0 = 0; g0 < 32; g0++) {
        int g = gb*32 + g0;
        float vv = vsm[g*32 + lane];
        #pragma unroll
        for (int r = 0; r < 2; r++) {
          float pwv = __shfl_sync(0xffffffffu, lg[r][gb], g0);
          accP[r][gb] = fmaf(pwv, vv, accP[r][gb]);
        }
      }
    }
    #pragma unroll
    for (int r = 0; r < 2; r++) {
      float acc = (accP[r][0]+accP[r][1]) + (accP[r][2]+accP[r][3]);
      g_att4[base + (size_t)(half*64 + warp*2 + r)*S_ + lane] = acc;
    }
  }
  grid_barrier(NB_, true);
  // reset mini-barrier counters for next pass / next graph replay
  if (blk < 16 && tid == 0) st_rlx_(&g_bcnt[blk], 0u);

  // ================= stage C: gate GEMM (fused head-mean+ReLU) ====================
  if (blk < 96) {
    float* as = pool;   // 16*128
    int gate = blk / 32, chunk = blk & 31;
    const float* Wm = (gate == 0) ? Wii : (gate == 1) ? Wig : Wio;
    int j0 = chunk*128;
    for (int i = tid; i < 16*128; i += 1024) {
      int bb = i >> 7, j = i & 127;
      size_t bbase = (size_t)bb*4*(H_*S_);
      int hs = j0 + j;
      float v = (g_att4[bbase + hs] + g_att4[bbase + 4096 + hs])
              + (g_att4[bbase + 8192 + hs] + g_att4[bbase + 12288 + hs]);
      v *= 0.25f;
      as[i] = v > 0.f ? v : 0.f;
    }
    __syncthreads();
    int m = tid & 127, oct = tid >> 7;   // oct 0..7, 2 batch rows each
    float acc[2][4];
    #pragma unroll
    for (int bbi = 0; bbi < 2; bbi++)
      #pragma unroll
      for (int jb = 0; jb < 4; jb++) acc[bbi][jb] = 0.f;
    #pragma unroll
    for (int jb = 0; jb < 4; jb++)
      #pragma unroll 8
      for (int j0i = 0; j0i < 32; j0i++) {
        int j = jb*32 + j0i;
        float w = Wm[(size_t)(j0+j)*H_ + m];
        #pragma unroll
        for (int bbi = 0; bbi < 2; bbi++)
          acc[bbi][jb] = fmaf(as[(oct*2+bbi)*128 + j], w, acc[bbi][jb]);
      }
    size_t cbase = ((size_t)(gate*32 + chunk))*(BB_*H_);
    #pragma unroll
    for (int bbi = 0; bbi < 2; bbi++)
      g_part[cbase + (oct*2+bbi)*H_ + m] =
        (acc[bbi][0]+acc[bbi][1]) + (acc[bbi][2]+acc[bbi][3]);
  }

  // barrier 3: blocks >= 16 arrive and exit; 0..15 continue to stage D'
  if (blk >= 16) { grid_barrier(NB_, false); return; }
  grid_barrier(NB_, true);

  // ================= stage D': per-b tail — reduce+LSTM+fc+reparam+KL(+dec) =======
  {
    float* s_g  = pool;          // 384
    float* s_h  = pool + 512;    // 128
    float* s_fc = pool + 768;    // 256
    float* s_z  = pool + 1024;   // 128
    float* h1   = pool + 1280;   // 128
    double* rd  = (double*)(pool + 2048);  // 128 doubles
    int b = blk;
    if (tid < 384) {
      int gate = tid >> 7, m = tid & 127;
      int r = b*128 + m;
      float s = 0.f, c = 0.f;
      #pragma unroll
      for (int ch = 0; ch < 32; ch++)
        kadd_(s, c, g_part[(size_t)(gate*32 + ch)*(BB_*H_) + r]);
      s_g[gate*128 + m] = s + c;
    }
    __syncthreads();
    if (tid < 128) {
      double iv = 1.0/(1.0 + exp(-(double)s_g[tid]));
      double gv = tanh((double)s_g[128 + tid]);
      double ov = 1.0/(1.0 + exp(-(double)s_g[256 + tid]));
      s_h[tid] = (float)(ov * tanh(iv * gv));
    }
    __syncthreads();
    if (tid < 256) {
      int c = tid;
      float s = 0.f, cc = 0.f;
      #pragma unroll 8
      for (int mm = 0; mm < 128; mm++)
        kadd_(s, cc, s_h[mm] * w_fc[mm*256 + c]);
      s_fc[c] = (s + cc) + b_fc[c];
    }
    __syncthreads();
    if (tid < 128) {
      int k = tid, idx = b*128 + k;
      float mu = s_fc[k];
      float lv = s_fc[128 + k];
      unsigned int o0, o1;
      threefry2x32_(0u, keylo, 0u, (unsigned int)idx, o0, o1);
      unsigned int bits = o0 ^ o1;
      float f = __uint_as_float((bits >> 9) | 0x3f800000u) - 1.0f;   // [0,1)
      const float lo = -0.99999994f;                                 // nextafter(-1,0)
      float u = fmaxf(lo, fmaf(f, 2.0f, lo));
      float eps = 1.4142135623730951f * erfinvf(u);
      float zv = fmaf(eps, expf(0.5f*lv), mu);
      z_out[idx] = zv;
      s_z[k] = zv;
      double dmu = (double)mu, dlv = (double)lv;
      rd[k] = 1.0 + dlv - dmu*dmu - exp(dlv);
    }
    __syncthreads();
    for (int o = 64; o; o >>= 1) {
      if (tid < o) rd[tid] += rd[tid + o];
      __syncthreads();
    }
    if (tid == 0) g_partKL[b] = rd[0];
    __syncthreads();
    if (b != 0 && tid == 0)
      atom_add_acqrel_(&g_klcnt, 1u);   // release partial KL

    if (do_dec) {
      if (tid < 128) {
        int c = tid;
        float p[4] = {0.f,0.f,0.f,0.f};
        #pragma unroll
        for (int jb = 0; jb < 4; jb++)
          #pragma unroll 8
          for (int j0 = 0; j0 < 32; j0++) {
            int j = jb*32 + j0;
            p[jb] = fmaf(s_z[j], w_d1[j*128+c], p[jb]);
          }
        h1[c] = fmaxf(((p[0]+p[1]) + (p[2]+p[3])) + b_d1[c], 0.f);
      }
      __syncthreads();
      if (tid < 128) {
        int c = tid;
        float p[4] = {0.f,0.f,0.f,0.f};
        #pragma unroll
        for (int jb = 0; jb < 4; jb++)
          #pragma unroll 8
          for (int j0 = 0; j0 < 32; j0++) {
            int j = jb*32 + j0;
            p[jb] = fmaf(h1[j], w_d2[j*128+c], p[jb]);
          }
        g_h2[b*128 + c] = fmaxf(((p[0]+p[1]) + (p[2]+p[3])) + b_d2[c], 0.f);
      }
    }

    // block 0 finalizes KL after all 15 partners arrive
    if (b == 0 && tid == 0) {
      while (ld_acq_(&g_klcnt) < 15u) { }
      double ks = 0.0;
      #pragma unroll
      for (int b2 = 0; b2 < 16; b2++) ks += g_partKL[b2];
      kl_out[0] = (float)(-0.5 * ks * (1.0/2048.0));
      st_rlx_(&g_klcnt, 0u);
    }
  }
}

// ---------------- big decode GEMM h2[16,128] @ w_d3[128,262144] + b_d3 ----------------
__device__ __forceinline__ unsigned long long pk2_(float a, float b){
  return (unsigned long long)__float_as_uint(a) | ((unsigned long long)__float_as_uint(b) << 32);
}

__global__ void __launch_bounds__(256) big_kernel(
    const float* __restrict__ w_d3, const float* __restrict__ b_d3, float* __restrict__ out)
{
  __shared__ unsigned long long hp[8*128];   // (b-pair, j) packed h2 values
  int tid = threadIdx.x;
  for (int i = tid; i < 1024; i += 256) {
    int p = i >> 7, j = i & 127;
    hp[i] = pk2_(g_h2[(2*p)*128 + j], g_h2[(2*p+1)*128 + j]);
  }
  __syncthreads();
  size_t m2 = (size_t)blockIdx.x*256 + tid;    // float2 column index, < 131072
  const float2* w2 = (const float2*)w_d3;
  float2 bv2 = ((const float2*)b_d3)[m2];
  unsigned long long accx[8], accy[8];
  unsigned long long bx = pk2_(bv2.x, bv2.x), by = pk2_(bv2.y, bv2.y);
  #pragma unroll
  for (int p = 0; p < 8; p++){ accx[p] = bx; accy[p] = by; }
  #pragma unroll 4
  for (int j = 0; j < 128; j++) {
    float2 w = __ldg(&w2[(size_t)j*131072 + m2]);
    unsigned long long wx = pk2_(w.x, w.x), wy = pk2_(w.y, w.y);
    #pragma unroll
    for (int p = 0; p < 8; p++) {
      unsigned long long hpair = hp[p*128 + j];
      asm("fma.rn.f32x2 %0, %1, %2, %3;" : "=l"(accx[p]) : "l"(hpair), "l"(wx), "l"(accx[p]));
      asm("fma.rn.f32x2 %0, %1, %2, %3;" : "=l"(accy[p]) : "l"(hpair), "l"(wy), "l"(accy[p]));
    }
  }
  float2* o2 = (float2*)out;
  #pragma unroll
  for (int p = 0; p < 8; p++) {
    float2 v0, v1;
    v0.x = __uint_as_float((unsigned int)accx[p]);
    v0.y = __uint_as_float((unsigned int)accy[p]);
    v1.x = __uint_as_float((unsigned int)(accx[p] >> 32));
    v1.y = __uint_as_float((unsigned int)(accy[p] >> 32));
    o2[(size_t)(2*p)*131072 + m2]   = v0;
    o2[(size_t)(2*p+1)*131072 + m2] = v1;
  }
}

// ---------------- launcher (3 launches total) ----------------
extern "C" void kernel_launch(void* const* d_in, const int* in_sizes, int n_in,
                              void* d_out, int out_size)
{
  (void)in_sizes; (void)n_in; (void)out_size;
  const float* x     = (const float*)d_in[0];
  const float* w_enc = (const float*)d_in[1];
  const float* b_enc = (const float*)d_in[2];
  const float* wq    = (const float*)d_in[3];
  const float* bq    = (const float*)d_in[4];
  const float* wk    = (const float*)d_in[5];
  const float* bk    = (const float*)d_in[6];
  const float* wv    = (const float*)d_in[7];
  const float* bv    = (const float*)d_in[8];
  const float* W_ii  = (const float*)d_in[9];
  const float* W_ig  = (const float*)d_in[13];
  const float* W_io  = (const float*)d_in[15];
  const float* w_fc  = (const float*)d_in[17];
  const float* b_fc  = (const float*)d_in[18];
  const float* w_d1  = (const float*)d_in[19];
  const float* b_d1  = (const float*)d_in[20];
  const float* w_d2  = (const float*)d_in[21];
  const float* b_d2  = (const float*)d_in[22];
  const float* w_d3  = (const float*)d_in[23];
  const float* b_d3  = (const float*)d_in[24];

  float* outp = (float*)d_out;
  float* xhat = outp;                  // [16,64,32,128] = 4194304
  float* z1   = outp + 4194304;        // [16,128]
  float* z2   = z1 + 2048;             // [16,128]
  float* kl1  = z2 + 2048;             // scalar
  float* kl2  = kl1 + 1;               // scalar

  // -------- pass 1: encode(x, key=1) + decode MLP --------
  enc_kernel<<<NB_, 1024>>>(x, w_enc, b_enc, wq, bq, wk, bk, wv, bv,
                            W_ii, W_ig, W_io, w_fc, b_fc,
                            1u, z1, kl1, 1, w_d1, b_d1, w_d2, b_d2);
  // -------- big decode GEMM --------
  big_kernel<<<512, 256>>>(w_d3, b_d3, xhat);
  // -------- pass 2: encode(x_hat1, key=2) --------
  enc_kernel<<<NB_, 1024>>>(xhat, w_enc, b_enc, wq, bq, wk, bk, wv, bv,
                            W_ii, W_ig, W_io, w_fc, b_fc,
                            2u, z2, kl2, 0, w_d1, b_d1, w_d2, b_d2);
}